// round 1
// baseline (speedup 1.0000x reference)
#include <cuda_runtime.h>
#include <math.h>

#define Nn 64
#define Cc 512
#define Tt 512
#define Kk 1024
#define NCT (Nn*Cc*Tt)

// ---------------- device scratch (no allocations allowed) ----------------
__device__ float  g_xt[NCT];     // x transposed (N,T,C)
__device__ float  g_res[NCT];    // residual (N,T,C)
__device__ float  g_fhat[NCT];   // f_hat accumulator (N,T,C)
__device__ float  g_rd[NCT];     // downsampled residual rows (M, C)
__device__ int    g_idx[Nn*(128+256+512)];
__device__ float  g_cbhalf[Kk];  // ||cb_k||^2 / 2
__device__ float  g_hist[Kk];
__device__ double g_err[3];
__device__ float  g_masksum;

// ---------------- transpose in: x (N,C,T) -> g_xt/g_res (N,T,C) ----------
__global__ void k_transpose_in(const float* __restrict__ x) {
    __shared__ float tile[32][33];
    int n  = blockIdx.z;
    int t0 = blockIdx.x * 32, c0 = blockIdx.y * 32;
    const float* xin = x + (size_t)n * Cc * Tt;
#pragma unroll
    for (int k = 0; k < 4; k++) {
        int c = c0 + threadIdx.y + k * 8;
        tile[threadIdx.y + k * 8][threadIdx.x] = xin[(size_t)c * Tt + t0 + threadIdx.x];
    }
    __syncthreads();
    float* xo = g_xt  + (size_t)n * Tt * Cc;
    float* ro = g_res + (size_t)n * Tt * Cc;
#pragma unroll
    for (int k = 0; k < 4; k++) {
        int t = t0 + threadIdx.y + k * 8;
        float v = tile[threadIdx.x][threadIdx.y + k * 8];
        size_t o = (size_t)t * Cc + c0 + threadIdx.x;
        xo[o] = v; ro[o] = v;
    }
}

// ---------------- transpose out: g_fhat (N,T,C) -> out (N,C,T) -----------
__global__ void k_transpose_out(float* __restrict__ out) {
    __shared__ float tile[32][33];
    int n  = blockIdx.z;
    int c0 = blockIdx.x * 32, t0 = blockIdx.y * 32;
    const float* fi = g_fhat + (size_t)n * Tt * Cc;
#pragma unroll
    for (int k = 0; k < 4; k++) {
        int t = t0 + threadIdx.y + k * 8;
        tile[threadIdx.y + k * 8][threadIdx.x] = fi[(size_t)t * Cc + c0 + threadIdx.x];
    }
    __syncthreads();
    float* oo = out + (size_t)n * Cc * Tt;
#pragma unroll
    for (int k = 0; k < 4; k++) {
        int c = c0 + threadIdx.y + k * 8;
        oo[(size_t)c * Tt + t0 + threadIdx.x] = tile[threadIdx.x][threadIdx.y + k * 8];
    }
}

// ---------------- codebook half-norms ------------------------------------
__global__ void k_cbhalf(const float* __restrict__ cb) {
    int k = blockIdx.x;
    const float* row = cb + (size_t)k * Cc;
    float s = 0.f;
    for (int i = threadIdx.x; i < Cc; i += 128) { float v = row[i]; s += v * v; }
#pragma unroll
    for (int o = 16; o; o >>= 1) s += __shfl_down_sync(0xffffffffu, s, o);
    __shared__ float ws[4];
    if ((threadIdx.x & 31) == 0) ws[threadIdx.x >> 5] = s;
    __syncthreads();
    if (threadIdx.x == 0) g_cbhalf[k] = 0.5f * (ws[0] + ws[1] + ws[2] + ws[3]);
}

// ---------------- scalar prep: mask sum + err reset -----------------------
__global__ void k_prep_scalars(const int* __restrict__ m_lens) {
    __shared__ int sm[Nn];
    if (threadIdx.x < Nn) sm[threadIdx.x] = m_lens[threadIdx.x];
    __syncthreads();
    if (threadIdx.x == 0) {
        int s = 0;
        for (int i = 0; i < Nn; i++) s += sm[i];
        g_masksum = (float)s;
    }
    if (threadIdx.x < 3) g_err[threadIdx.x] = 0.0;
}

__global__ void k_reset_hist() {
    g_hist[blockIdx.x * 256 + threadIdx.x] = 0.f;
}

// ---------------- mask + average-pool residual -> g_rd -------------------
__global__ void k_downsample(const int* __restrict__ m_lens, int s, int t) {
    int row = blockIdx.x;
    int n = row / t, tp = row % t;
    int ml = m_lens[n];
    const float4* src = (const float4*)(g_res + ((size_t)n * Tt + (size_t)tp * s) * Cc);
    float4* dst = (float4*)(g_rd + (size_t)row * Cc);
    float inv = 1.0f / (float)s;
    int i = threadIdx.x;            // 128 threads == C/4
    float4 acc = make_float4(0.f, 0.f, 0.f, 0.f);
    for (int j = 0; j < s; j++) {
        if (tp * s + j < ml) {
            float4 v = src[(size_t)j * (Cc / 4) + i];
            acc.x += v.x; acc.y += v.y; acc.z += v.z; acc.w += v.w;
        }
    }
    dst[i] = make_float4(acc.x * inv, acc.y * inv, acc.z * inv, acc.w * inv);
}

// ---------------- quantize: argmax_k (v . cb_k - ||cb_k||^2/2) ------------
// Block: 64 rows x all K. A tile (64x512) resident in smem (transposed,
// padded stride 68 for float4 + bank spread). B streamed in 64x16 tiles.
#define ASTRIDE 68
#define QSM_A (Cc * ASTRIDE)      // 34816 floats
#define QSM_B (16 * ASTRIDE)      // 1088 floats
#define QSM_BYTES ((QSM_A + QSM_B) * 4)

__global__ void k_quantize(const float* __restrict__ cb,
                           const int* __restrict__ m_lens,
                           int t, int scale, int* __restrict__ idx_out) {
    extern __shared__ float sm[];
    float* As = sm;
    float* Bs = sm + QSM_A;
    int mbase = blockIdx.x * 64;
    int n = mbase / t;                 // t % 64 == 0 -> single n per block
    int tlim = m_lens[n] / scale;
    int trow0 = mbase % t;
    if (trow0 >= tlim) return;         // fully masked tile: outputs unused

    const float* Ag = g_rd + (size_t)mbase * Cc;
#pragma unroll 8
    for (int r = 0; r < 128; r++) {
        int i = threadIdx.x + r * 256;
        int m = i >> 9, c = i & 511;
        As[c * ASTRIDE + m] = Ag[i];
    }
    __syncthreads();

    int tm  = (threadIdx.x >> 4) << 2;   // row group (0..60 step 4)
    int tn4 = (threadIdx.x & 15) << 2;   // col group within 64-tile
    float best[4] = {-1e30f, -1e30f, -1e30f, -1e30f};
    int   bidx[4] = {0, 0, 0, 0};

    for (int nt = 0; nt < Kk; nt += 64) {
        float acc[4][4];
#pragma unroll
        for (int i = 0; i < 4; i++)
#pragma unroll
            for (int j = 0; j < 4; j++) acc[i][j] = 0.f;

        for (int ko = 0; ko < Cc; ko += 16) {
            __syncthreads();
#pragma unroll
            for (int r = 0; r < 4; r++) {
                int i = threadIdx.x + r * 256;
                int nn = i >> 4, kk = i & 15;
                Bs[kk * ASTRIDE + nn] = cb[(size_t)(nt + nn) * Cc + ko + kk];
            }
            __syncthreads();
#pragma unroll
            for (int kk = 0; kk < 16; kk++) {
                float4 a = *(const float4*)(As + (ko + kk) * ASTRIDE + tm);
                float4 b = *(const float4*)(Bs + kk * ASTRIDE + tn4);
                float a4[4] = {a.x, a.y, a.z, a.w};
                float b4[4] = {b.x, b.y, b.z, b.w};
#pragma unroll
                for (int i = 0; i < 4; i++)
#pragma unroll
                    for (int j = 0; j < 4; j++)
                        acc[i][j] = fmaf(a4[i], b4[j], acc[i][j]);
            }
        }
#pragma unroll
        for (int j = 0; j < 4; j++) {
            int k = nt + tn4 + j;
            float ch = g_cbhalf[k];
#pragma unroll
            for (int i = 0; i < 4; i++) {
                float v = acc[i][j] - ch;
                if (v > best[i]) { best[i] = v; bidx[i] = k; }  // strict >: first max wins
            }
        }
    }

    __syncthreads();                   // done reading As; reuse smem
    float* rv = sm;                    // [64][16]
    int*   ri = (int*)(sm + 1024);     // [64][16]
    int ct = threadIdx.x & 15;
#pragma unroll
    for (int i = 0; i < 4; i++) {
        rv[(tm + i) * 16 + ct] = best[i];
        ri[(tm + i) * 16 + ct] = bidx[i];
    }
    __syncthreads();
    if (threadIdx.x < 64) {
        int row = threadIdx.x;
        float bv = rv[row * 16]; int bi = ri[row * 16];
        for (int c2 = 1; c2 < 16; c2++) {
            float v = rv[row * 16 + c2]; int ii = ri[row * 16 + c2];
            if (v > bv || (v == bv && ii < bi)) { bv = v; bi = ii; }
        }
        idx_out[mbase + row] = (trow0 + row < tlim) ? bi : 0;
    }
}

// ---------------- masked histogram of codeword usage ---------------------
__global__ void k_hist(const int* __restrict__ m_lens, int t, int scale,
                       const int* __restrict__ idxbuf, int M) {
    int r = blockIdx.x * 256 + threadIdx.x;
    if (r >= M) return;
    int n = r / t, tr = r % t;
    if (tr < m_lens[n] / scale) atomicAdd(&g_hist[idxbuf[r]], 1.0f);
}

// ---------------- upsample + residual/f_hat update + loss ----------------
__global__ void k_update(const float* __restrict__ cb,
                         const int* __restrict__ m_lens,
                         int s, int t, const int* __restrict__ idxbuf, int sid) {
    int g = blockIdx.x;
    int n = g / Tt, j = g % Tt;
    int ml = m_lens[n];
    int tlim = ml / s;
    float pos = (j + 0.5f) / (float)s - 0.5f;
    pos = fminf(fmaxf(pos, 0.0f), (float)(t - 1));
    int lo = (int)floorf(pos);
    int hi = min(lo + 1, t - 1);
    float w = pos - (float)lo;
    const int* idxn = idxbuf + n * t;
    int ilo = (lo < tlim) ? idxn[lo] : -1;
    int ihi = (hi < tlim) ? idxn[hi] : -1;
    float wl = 1.0f - w, wh = w;
    bool mask = (j < ml);
    float mm = mask ? 1.0f : 0.0f;

    size_t base = ((size_t)n * Tt + j) * (Cc / 4);
    float4* resp = ((float4*)g_res) + base;
    float4* fhp  = ((float4*)g_fhat) + base;
    const float4* xtp = ((const float4*)g_xt) + base;
    const float4* clo = (const float4*)(cb + (size_t)max(ilo, 0) * Cc);
    const float4* chi = (const float4*)(cb + (size_t)max(ihi, 0) * Cc);

    int i = threadIdx.x;               // 128 threads == C/4
    float4 up = make_float4(0.f, 0.f, 0.f, 0.f);
    if (ilo >= 0) { float4 v = clo[i]; up.x += wl * v.x; up.y += wl * v.y; up.z += wl * v.z; up.w += wl * v.w; }
    if (ihi >= 0) { float4 v = chi[i]; up.x += wh * v.x; up.y += wh * v.y; up.z += wh * v.z; up.w += wh * v.w; }

    float4 r4 = resp[i];
    float4 rn = make_float4(r4.x * mm - up.x, r4.y * mm - up.y,
                            r4.z * mm - up.z, r4.w * mm - up.w);
    float4 f4 = fhp[i];
    float4 fn = make_float4(f4.x + up.x, f4.y + up.y, f4.z + up.z, f4.w + up.w);
    resp[i] = rn;
    fhp[i]  = fn;

    float lsum = 0.f;
    if (mask) {
        float4 xv = xtp[i];
        float ex = xv.x - fn.x, ey = xv.y - fn.y, ez = xv.z - fn.z, ew = xv.w - fn.w;
        lsum = ex * ex + ey * ey + ez * ez + ew * ew;
    }
#pragma unroll
    for (int o = 16; o; o >>= 1) lsum += __shfl_down_sync(0xffffffffu, lsum, o);
    __shared__ float ws[4];
    if ((threadIdx.x & 31) == 0) ws[threadIdx.x >> 5] = lsum;
    __syncthreads();
    if (threadIdx.x == 0 && mask)
        atomicAdd(&g_err[sid], (double)(ws[0] + ws[1] + ws[2] + ws[3]));
}

// ---------------- finalize: loss + perplexity ----------------------------
__global__ void k_finalize(float* __restrict__ out) {
    int tid = threadIdx.x;             // 1024 threads, K = 1024
    float c = g_hist[tid];
    __shared__ float ws[32];
    float v = c;
#pragma unroll
    for (int o = 16; o; o >>= 1) v += __shfl_down_sync(0xffffffffu, v, o);
    if ((tid & 31) == 0) ws[tid >> 5] = v;
    __syncthreads();
    if (tid < 32) {
        float z = ws[tid];
#pragma unroll
        for (int o = 16; o; o >>= 1) z += __shfl_down_sync(0xffffffffu, z, o);
        if (tid == 0) ws[0] = z;
    }
    __syncthreads();
    float total = ws[0];
    __syncthreads();
    float p = c / total;
    float e = p * logf(p + 1e-7f);
#pragma unroll
    for (int o = 16; o; o >>= 1) e += __shfl_down_sync(0xffffffffu, e, o);
    if ((tid & 31) == 0) ws[tid >> 5] = e;
    __syncthreads();
    if (tid == 0) {
        float ent = 0.f;
        for (int i = 0; i < 32; i++) ent += ws[i];
        double denom = (double)g_masksum * (double)Tt;
        double loss = (g_err[0] + g_err[1] + g_err[2]) / denom / 3.0;
        out[NCT]     = (float)loss;
        out[NCT + 1] = expf(-ent);
    }
}

// ---------------- launch ---------------------------------------------------
extern "C" void kernel_launch(void* const* d_in, const int* in_sizes, int n_in,
                              void* d_out, int out_size) {
    // identify inputs by element count (x: NCT, codebook: K*C, m_lens: N)
    const float* x = nullptr; const float* cb = nullptr; const int* m_lens = nullptr;
    for (int i = 0; i < n_in; i++) {
        if (in_sizes[i] == NCT)            x = (const float*)d_in[i];
        else if (in_sizes[i] == Kk * Cc)   cb = (const float*)d_in[i];
        else if (in_sizes[i] == Nn)        m_lens = (const int*)d_in[i];
    }
    float* out = (float*)d_out;

    cudaFuncSetAttribute(k_quantize, cudaFuncAttributeMaxDynamicSharedMemorySize, QSM_BYTES);

    void* fh = nullptr;
    cudaGetSymbolAddress(&fh, g_fhat);
    cudaMemsetAsync(fh, 0, sizeof(float) * NCT, 0);

    void* idxv = nullptr;
    cudaGetSymbolAddress(&idxv, g_idx);
    int* idxbase = (int*)idxv;

    k_reset_hist<<<4, 256>>>();
    k_prep_scalars<<<1, 64>>>(m_lens);
    k_cbhalf<<<Kk, 128>>>(cb);
    {
        dim3 gb(Tt / 32, Cc / 32, Nn), tb(32, 8);
        k_transpose_in<<<gb, tb>>>(x);
    }

    const int scales[3] = {4, 2, 1};
    const int offs[3]   = {0, Nn * 128, Nn * 128 + Nn * 256};
    for (int s = 0; s < 3; s++) {
        int sc = scales[s], t = Tt / sc, M = Nn * t;
        int* idxp = idxbase + offs[s];
        k_downsample<<<M, 128>>>(m_lens, sc, t);
        k_quantize<<<M / 64, 256, QSM_BYTES>>>(cb, m_lens, t, sc, idxp);
        k_hist<<<(M + 255) / 256, 256>>>(m_lens, t, sc, idxp, M);
        k_update<<<Nn * Tt, 128>>>(cb, m_lens, sc, t, idxp, s);
    }

    k_finalize<<<1, 1024>>>(out);
    {
        dim3 gb(Cc / 32, Tt / 32, Nn), tb(32, 8);
        k_transpose_out<<<gb, tb>>>(out);
    }
}

// round 2
// speedup vs baseline: 1.5852x; 1.5852x over previous
#include <cuda_runtime.h>
#include <math.h>

#define Nn 64
#define Cc 512
#define Tt 512
#define Kk 1024
#define NCT (Nn*Cc*Tt)

typedef unsigned long long ull;

// ---------------- device scratch (no allocations allowed) ----------------
__device__ float  g_xt[NCT];     // x transposed (N,T,C)
__device__ float  g_res[NCT];    // residual (N,T,C)
__device__ float  g_fhat[NCT];   // f_hat accumulator (N,T,C)
__device__ float  g_rdT[NCT];    // downsampled residual, blocked col-major [rb][512][128]
__device__ float  g_cbT[Kk*Cc];  // codebook, blocked col-major [kb][512][128]
__device__ int    g_idx[Nn*(128+256+512)];
__device__ float  g_cbhalf[Kk];  // ||cb_k||^2 / 2
__device__ float  g_hist[Kk];
__device__ double g_err[3];
__device__ float  g_masksum;
__device__ float  g_pval[32768 * 4];
__device__ int    g_pidx[32768 * 4];

// ---------------- transpose in: x (N,C,T) -> g_xt/g_res (N,T,C) ----------
__global__ void k_transpose_in(const float* __restrict__ x) {
    __shared__ float tile[32][33];
    int n  = blockIdx.z;
    int t0 = blockIdx.x * 32, c0 = blockIdx.y * 32;
    const float* xin = x + (size_t)n * Cc * Tt;
#pragma unroll
    for (int k = 0; k < 4; k++) {
        int c = c0 + threadIdx.y + k * 8;
        tile[threadIdx.y + k * 8][threadIdx.x] = xin[(size_t)c * Tt + t0 + threadIdx.x];
    }
    __syncthreads();
    float* xo = g_xt  + (size_t)n * Tt * Cc;
    float* ro = g_res + (size_t)n * Tt * Cc;
#pragma unroll
    for (int k = 0; k < 4; k++) {
        int t = t0 + threadIdx.y + k * 8;
        float v = tile[threadIdx.x][threadIdx.y + k * 8];
        size_t o = (size_t)t * Cc + c0 + threadIdx.x;
        xo[o] = v; ro[o] = v;
    }
}

// ---------------- transpose out: g_fhat (N,T,C) -> out (N,C,T) -----------
__global__ void k_transpose_out(float* __restrict__ out) {
    __shared__ float tile[32][33];
    int n  = blockIdx.z;
    int c0 = blockIdx.x * 32, t0 = blockIdx.y * 32;
    const float* fi = g_fhat + (size_t)n * Tt * Cc;
#pragma unroll
    for (int k = 0; k < 4; k++) {
        int t = t0 + threadIdx.y + k * 8;
        tile[threadIdx.y + k * 8][threadIdx.x] = fi[(size_t)t * Cc + c0 + threadIdx.x];
    }
    __syncthreads();
    float* oo = out + (size_t)n * Cc * Tt;
#pragma unroll
    for (int k = 0; k < 4; k++) {
        int c = c0 + threadIdx.y + k * 8;
        oo[(size_t)c * Tt + t0 + threadIdx.x] = tile[threadIdx.x][threadIdx.y + k * 8];
    }
}

// ---------------- codebook: half norms + blocked transpose ---------------
__global__ void k_cbhalf(const float* __restrict__ cb) {
    int k = blockIdx.x;
    const float* row = cb + (size_t)k * Cc;
    float s = 0.f;
    for (int i = threadIdx.x; i < Cc; i += 128) { float v = row[i]; s += v * v; }
#pragma unroll
    for (int o = 16; o; o >>= 1) s += __shfl_down_sync(0xffffffffu, s, o);
    __shared__ float ws[4];
    if ((threadIdx.x & 31) == 0) ws[threadIdx.x >> 5] = s;
    __syncthreads();
    if (threadIdx.x == 0) g_cbhalf[k] = 0.5f * (ws[0] + ws[1] + ws[2] + ws[3]);
}

// cb (K,C) row-major -> g_cbT blocked [kb][c][k%128]
__global__ void k_cb_transpose(const float* __restrict__ cb) {
    __shared__ float tile[32][33];
    int k0 = blockIdx.x * 32, c0 = blockIdx.y * 32;
#pragma unroll
    for (int q = 0; q < 4; q++) {
        int k = k0 + threadIdx.y + q * 8;
        tile[threadIdx.y + q * 8][threadIdx.x] = cb[(size_t)k * Cc + c0 + threadIdx.x];
    }
    __syncthreads();
#pragma unroll
    for (int q = 0; q < 4; q++) {
        int c = c0 + threadIdx.y + q * 8;
        int k = k0 + threadIdx.x;
        g_cbT[(size_t)(k >> 7) * (Cc * 128) + (size_t)c * 128 + (k & 127)] =
            tile[threadIdx.x][threadIdx.y + q * 8];
    }
}

// ---------------- scalar prep -----------------------------------------
__global__ void k_prep_scalars(const int* __restrict__ m_lens) {
    __shared__ int sm[Nn];
    if (threadIdx.x < Nn) sm[threadIdx.x] = m_lens[threadIdx.x];
    __syncthreads();
    if (threadIdx.x == 0) {
        int s = 0;
        for (int i = 0; i < Nn; i++) s += sm[i];
        g_masksum = (float)s;
    }
    if (threadIdx.x < 3) g_err[threadIdx.x] = 0.0;
}

__global__ void k_reset_hist() { g_hist[blockIdx.x * 256 + threadIdx.x] = 0.f; }

// ------- mask + avg-pool residual, written blocked col-major -------------
// g_rdT layout: [row_block(128)][c(512)][row_in_block(128)]
__global__ void k_downsampleT(const int* __restrict__ m_lens, int s, int t) {
    __shared__ float tile[32][33];
    int r0 = blockIdx.x * 32;
    int c0 = blockIdx.y * 32;
    float inv = 1.0f / (float)s;
#pragma unroll
    for (int q = 0; q < 4; q++) {
        int r = r0 + threadIdx.y + q * 8;          // global row
        int n = r / t, tp = r % t;
        int ml = m_lens[n];
        int c = c0 + threadIdx.x;
        const float* src = g_res + ((size_t)n * Tt + (size_t)tp * s) * Cc + c;
        float acc = 0.f;
        for (int j = 0; j < s; j++)
            if (tp * s + j < ml) acc += src[(size_t)j * Cc];
        tile[threadIdx.y + q * 8][threadIdx.x] = acc * inv;
    }
    __syncthreads();
#pragma unroll
    for (int q = 0; q < 4; q++) {
        int c = c0 + threadIdx.y + q * 8;
        int r = r0 + threadIdx.x;
        g_rdT[(size_t)(r >> 7) * (Cc * 128) + (size_t)c * 128 + (r & 127)] =
            tile[threadIdx.x][threadIdx.y + q * 8];
    }
}

// ---------------- quantize v2: FFMA2 + cp.async double-buffer ------------
// Block: 128 rows x 128 cols, 256 threads, 8x8 per thread via f32x2.
__device__ __forceinline__ void cpa16(float* dst, const float* src) {
    unsigned sa = (unsigned)__cvta_generic_to_shared(dst);
    asm volatile("cp.async.cg.shared.global [%0], [%1], 16;" :: "r"(sa), "l"(src));
}
__device__ __forceinline__ void load_stage(float* As, float* Bs,
                                           const float* Ag, const float* Bg, int tid) {
#pragma unroll
    for (int q = 0; q < 4; q++) { int c = tid + q * 256; cpa16(As + c * 4, Ag + c * 4); }
#pragma unroll
    for (int q = 0; q < 4; q++) { int c = tid + q * 256; cpa16(Bs + c * 4, Bg + c * 4); }
    asm volatile("cp.async.commit_group;" ::: "memory");
}

#define FMA2(d, a, b) asm volatile("fma.rn.f32x2 %0, %1, %2, %0;" : "+l"(d) : "l"(a), "l"(b))

__global__ void __launch_bounds__(256, 1)
k_quantize2(const int* __restrict__ m_lens, int t, int scale, int nsplit,
            float* __restrict__ pval, int* __restrict__ pidx) {
    extern __shared__ float smem[];
    __shared__ float s_cbh[Kk];
    float* A0 = smem;
    float* B0 = smem + 4096;
    float* A1 = smem + 8192;
    float* B1 = smem + 12288;

    int tid = threadIdx.x;
    int mbase = blockIdx.x * 128;
    int n = mbase / t;                  // t % 128 == 0
    int tlim = m_lens[n] / scale;
    int trow0 = mbase % t;
    if (trow0 >= tlim) return;          // fully masked block

#pragma unroll
    for (int q = 0; q < 4; q++) s_cbh[tid + q * 256] = g_cbhalf[tid + q * 256];

    int tm = (tid & 15) * 8;            // 8 rows
    int tn = (tid >> 4) * 8;            // 8 cols within 128-tile
    int ntiles = 8 / nsplit;
    int nt0 = blockIdx.y * ntiles;

    const float* Agb = g_rdT + (size_t)blockIdx.x * (Cc * 128);

    float best[8];
    int   bidx[8];
#pragma unroll
    for (int i = 0; i < 8; i++) { best[i] = -1e30f; bidx[i] = 0; }

    for (int ti = 0; ti < ntiles; ti++) {
        int nt = nt0 + ti;
        const float* Bgb = g_cbT + (size_t)nt * (Cc * 128);

        ull acc[4][8];
#pragma unroll
        for (int i = 0; i < 4; i++)
#pragma unroll
            for (int j = 0; j < 8; j++) acc[i][j] = 0ull;

        load_stage(A0, B0, Agb, Bgb, tid);

        for (int ko = 0; ko < 16; ko++) {
            float* Ab = (ko & 1) ? A1 : A0;
            float* Bb = (ko & 1) ? B1 : B0;
            if (ko < 15) {
                float* An = (ko & 1) ? A0 : A1;
                float* Bn = (ko & 1) ? B0 : B1;
                load_stage(An, Bn, Agb + (ko + 1) * 4096, Bgb + (ko + 1) * 4096, tid);
                asm volatile("cp.async.wait_group 1;" ::: "memory");
            } else {
                asm volatile("cp.async.wait_group 0;" ::: "memory");
            }
            __syncthreads();

#pragma unroll 8
            for (int kk = 0; kk < 32; kk++) {
                const ulonglong2* ap =
                    reinterpret_cast<const ulonglong2*>(Ab + kk * 128 + tm);
                ulonglong2 av0 = ap[0];
                ulonglong2 av1 = ap[1];
                ull a[4] = {av0.x, av0.y, av1.x, av1.y};

                const float4* bp = reinterpret_cast<const float4*>(Bb + kk * 128 + tn);
                float4 bv0 = bp[0];
                float4 bv1 = bp[1];
                float bf[8] = {bv0.x, bv0.y, bv0.z, bv0.w, bv1.x, bv1.y, bv1.z, bv1.w};
                ull bd[8];
#pragma unroll
                for (int j = 0; j < 8; j++)
                    asm volatile("mov.b64 %0, {%1, %1};"
                                 : "=l"(bd[j]) : "r"(__float_as_uint(bf[j])));
#pragma unroll
                for (int i = 0; i < 4; i++)
#pragma unroll
                    for (int j = 0; j < 8; j++)
                        FMA2(acc[i][j], a[i], bd[j]);
            }
            __syncthreads();
        }

        // epilogue for this 128-col tile: subtract half-norm, update argmax
#pragma unroll
        for (int j = 0; j < 8; j++) {
            int col = nt * 128 + tn + j;
            float ch = s_cbh[col];
#pragma unroll
            for (int i = 0; i < 4; i++) {
                unsigned lo, hi;
                asm volatile("mov.b64 {%0, %1}, %2;" : "=r"(lo), "=r"(hi) : "l"(acc[i][j]));
                float v0 = __uint_as_float(lo) - ch;
                float v1 = __uint_as_float(hi) - ch;
                if (v0 > best[2 * i])     { best[2 * i] = v0;     bidx[2 * i] = col; }
                if (v1 > best[2 * i + 1]) { best[2 * i + 1] = v1; bidx[2 * i + 1] = col; }
            }
        }
    }

    // cross-thread reduction: 16 candidate threads per row
    __syncthreads();
    float* rv = smem;                 // [128][16]
    int*   ri = (int*)(smem + 2048);  // [128][16]
    int g = tid >> 4;
#pragma unroll
    for (int i = 0; i < 8; i++) {
        rv[(tm + i) * 16 + g] = best[i];
        ri[(tm + i) * 16 + g] = bidx[i];
    }
    __syncthreads();
    if (tid < 128) {
        float bv = rv[tid * 16]; int bi = ri[tid * 16];
        for (int c2 = 1; c2 < 16; c2++) {
            float v = rv[tid * 16 + c2]; int ii = ri[tid * 16 + c2];
            if (v > bv || (v == bv && ii < bi)) { bv = v; bi = ii; }
        }
        int row = mbase + tid;
        pval[row * nsplit + blockIdx.y] = bv;
        pidx[row * nsplit + blockIdx.y] = bi;
    }
}

// ---------------- combine K-split partials --------------------------------
__global__ void k_argreduce(const float* __restrict__ pval, const int* __restrict__ pidx,
                            int nsplit, int* __restrict__ idx_out, int M) {
    int r = blockIdx.x * 256 + threadIdx.x;
    if (r >= M) return;
    float bv = pval[r * nsplit]; int bi = pidx[r * nsplit];
    for (int s = 1; s < nsplit; s++) {
        float v = pval[r * nsplit + s]; int ii = pidx[r * nsplit + s];
        if (v > bv || (v == bv && ii < bi)) { bv = v; bi = ii; }
    }
    idx_out[r] = bi;
}

// ---------------- masked histogram ----------------------------------------
__global__ void k_hist(const int* __restrict__ m_lens, int t, int scale,
                       const int* __restrict__ idxbuf, int M) {
    int r = blockIdx.x * 256 + threadIdx.x;
    if (r >= M) return;
    int n = r / t, tr = r % t;
    if (tr < m_lens[n] / scale) atomicAdd(&g_hist[idxbuf[r]], 1.0f);
}

// ---------------- upsample + residual/f_hat update + loss ----------------
__global__ void k_update(const float* __restrict__ cb,
                         const int* __restrict__ m_lens,
                         int s, int t, const int* __restrict__ idxbuf, int sid) {
    int g = blockIdx.x;
    int n = g / Tt, j = g % Tt;
    int ml = m_lens[n];
    int tlim = ml / s;
    float pos = (j + 0.5f) / (float)s - 0.5f;
    pos = fminf(fmaxf(pos, 0.0f), (float)(t - 1));
    int lo = (int)floorf(pos);
    int hi = min(lo + 1, t - 1);
    float w = pos - (float)lo;
    const int* idxn = idxbuf + n * t;
    int ilo = (lo < tlim) ? idxn[lo] : -1;
    int ihi = (hi < tlim) ? idxn[hi] : -1;
    float wl = 1.0f - w, wh = w;
    bool mask = (j < ml);
    float mm = mask ? 1.0f : 0.0f;

    size_t base = ((size_t)n * Tt + j) * (Cc / 4);
    float4* resp = ((float4*)g_res) + base;
    float4* fhp  = ((float4*)g_fhat) + base;
    const float4* xtp = ((const float4*)g_xt) + base;
    const float4* clo = (const float4*)(cb + (size_t)max(ilo, 0) * Cc);
    const float4* chi = (const float4*)(cb + (size_t)max(ihi, 0) * Cc);

    int i = threadIdx.x;               // 128 threads == C/4
    float4 up = make_float4(0.f, 0.f, 0.f, 0.f);
    if (ilo >= 0) { float4 v = clo[i]; up.x += wl * v.x; up.y += wl * v.y; up.z += wl * v.z; up.w += wl * v.w; }
    if (ihi >= 0) { float4 v = chi[i]; up.x += wh * v.x; up.y += wh * v.y; up.z += wh * v.z; up.w += wh * v.w; }

    float4 r4 = resp[i];
    float4 rn = make_float4(r4.x * mm - up.x, r4.y * mm - up.y,
                            r4.z * mm - up.z, r4.w * mm - up.w);
    float4 f4 = fhp[i];
    float4 fn = make_float4(f4.x + up.x, f4.y + up.y, f4.z + up.z, f4.w + up.w);
    resp[i] = rn;
    fhp[i]  = fn;

    float lsum = 0.f;
    if (mask) {
        float4 xv = xtp[i];
        float ex = xv.x - fn.x, ey = xv.y - fn.y, ez = xv.z - fn.z, ew = xv.w - fn.w;
        lsum = ex * ex + ey * ey + ez * ez + ew * ew;
    }
#pragma unroll
    for (int o = 16; o; o >>= 1) lsum += __shfl_down_sync(0xffffffffu, lsum, o);
    __shared__ float ws[4];
    if ((threadIdx.x & 31) == 0) ws[threadIdx.x >> 5] = lsum;
    __syncthreads();
    if (threadIdx.x == 0 && mask)
        atomicAdd(&g_err[sid], (double)(ws[0] + ws[1] + ws[2] + ws[3]));
}

// ---------------- finalize: loss + perplexity ----------------------------
__global__ void k_finalize(float* __restrict__ out) {
    int tid = threadIdx.x;             // 1024 threads, K = 1024
    float c = g_hist[tid];
    __shared__ float ws[32];
    float v = c;
#pragma unroll
    for (int o = 16; o; o >>= 1) v += __shfl_down_sync(0xffffffffu, v, o);
    if ((tid & 31) == 0) ws[tid >> 5] = v;
    __syncthreads();
    if (tid < 32) {
        float z = ws[tid];
#pragma unroll
        for (int o = 16; o; o >>= 1) z += __shfl_down_sync(0xffffffffu, z, o);
        if (tid == 0) ws[0] = z;
    }
    __syncthreads();
    float total = ws[0];
    __syncthreads();
    float p = c / total;
    float e = p * logf(p + 1e-7f);
#pragma unroll
    for (int o = 16; o; o >>= 1) e += __shfl_down_sync(0xffffffffu, e, o);
    if ((tid & 31) == 0) ws[tid >> 5] = e;
    __syncthreads();
    if (tid == 0) {
        float ent = 0.f;
        for (int i = 0; i < 32; i++) ent += ws[i];
        double denom = (double)g_masksum * (double)Tt;
        double loss = (g_err[0] + g_err[1] + g_err[2]) / denom / 3.0;
        out[NCT]     = (float)loss;
        out[NCT + 1] = expf(-ent);
    }
}

// ---------------- launch ---------------------------------------------------
extern "C" void kernel_launch(void* const* d_in, const int* in_sizes, int n_in,
                              void* d_out, int out_size) {
    const float* x = nullptr; const float* cb = nullptr; const int* m_lens = nullptr;
    for (int i = 0; i < n_in; i++) {
        if (in_sizes[i] == NCT)            x = (const float*)d_in[i];
        else if (in_sizes[i] == Kk * Cc)   cb = (const float*)d_in[i];
        else if (in_sizes[i] == Nn)        m_lens = (const int*)d_in[i];
    }
    float* out = (float*)d_out;

    static bool attr_set = false;
    if (!attr_set) {
        cudaFuncSetAttribute(k_quantize2, cudaFuncAttributeMaxDynamicSharedMemorySize, 65536);
        attr_set = true;
    }

    void* fh = nullptr;
    cudaGetSymbolAddress(&fh, g_fhat);
    cudaMemsetAsync(fh, 0, sizeof(float) * NCT, 0);

    void* idxv = nullptr;  cudaGetSymbolAddress(&idxv, g_idx);
    int* idxbase = (int*)idxv;
    void* pvv = nullptr;   cudaGetSymbolAddress(&pvv, g_pval);
    float* pval = (float*)pvv;
    void* piv = nullptr;   cudaGetSymbolAddress(&piv, g_pidx);
    int* pidx = (int*)piv;

    k_reset_hist<<<4, 256>>>();
    k_prep_scalars<<<1, 64>>>(m_lens);
    k_cbhalf<<<Kk, 128>>>(cb);
    {
        dim3 gb(Kk / 32, Cc / 32), tb(32, 8);
        k_cb_transpose<<<gb, tb>>>(cb);
    }
    {
        dim3 gb(Tt / 32, Cc / 32, Nn), tb(32, 8);
        k_transpose_in<<<gb, tb>>>(x);
    }

    const int scales[3]  = {4, 2, 1};
    const int nsplits[3] = {4, 2, 1};
    const int offs[3]    = {0, Nn * 128, Nn * 128 + Nn * 256};
    for (int s = 0; s < 3; s++) {
        int sc = scales[s], t = Tt / sc, M = Nn * t;
        int nsplit = nsplits[s];
        int* idxp = idxbase + offs[s];
        {
            dim3 gb(M / 32, Cc / 32), tb(32, 8);
            k_downsampleT<<<gb, tb>>>(m_lens, sc, t);
        }
        k_quantize2<<<dim3(M / 128, nsplit), 256, 65536>>>(m_lens, t, sc, nsplit, pval, pidx);
        k_argreduce<<<M / 256, 256>>>(pval, pidx, nsplit, idxp, M);
        k_hist<<<(M + 255) / 256, 256>>>(m_lens, t, sc, idxp, M);
        k_update<<<Nn * Tt, 128>>>(cb, m_lens, sc, t, idxp, s);
    }

    k_finalize<<<1, 1024>>>(out);
    {
        dim3 gb(Cc / 32, Tt / 32, Nn), tb(32, 8);
        k_transpose_out<<<gb, tb>>>(out);
    }
}

// round 5
// speedup vs baseline: 2.5127x; 1.5851x over previous
#include <cuda_runtime.h>
#include <cuda_bf16.h>
#include <math.h>

#define Nn 64
#define Cc 512
#define Tt 512
#define Kk 1024
#define NCT (Nn*Cc*Tt)

#define NCHUNK 24               // stored: 3 splits x 8 chunks of 64 k
#define NSEG 6                  // GEMM segments: (h,h)(h,m)(m,h)(m,m)(h,l)(l,h)
#define GCHUNK (NSEG*8)         // 48 logical GEMM chunks
#define CHUNK_BYTES 16384       // 128 rows x 64 bf16 (SW128-swizzled)
#define PANEL_BYTES (NCHUNK*CHUNK_BYTES)
#define PANEL_ELEMS (NCHUNK*8192)

typedef unsigned int u32;
typedef unsigned long long u64;

__constant__ int c_mapA[NSEG] = {0, 0, 1, 1, 0, 2};
__constant__ int c_mapB[NSEG] = {0, 1, 0, 1, 2, 0};

// ---------------- device scratch ------------------------------------------
__device__ float  g_xt[NCT];
__device__ float  g_res[NCT];
__device__ float  g_fhat[NCT];
__device__ __align__(16) __nv_bfloat16 g_rdS[256 * PANEL_ELEMS]; // split A panels
__device__ __align__(16) __nv_bfloat16 g_cbS[8   * PANEL_ELEMS]; // split B panels
__device__ int    g_idx[Nn*(128+256+512)];
__device__ float  g_cbhalf[Kk];
__device__ float  g_hist[Kk];
__device__ double g_err[3];
__device__ float  g_masksum;
__device__ float  g_pval[32768 * 8];
__device__ int    g_pidx[32768 * 8];

// ---------------- PTX helpers ---------------------------------------------
__device__ __forceinline__ u32 smem_u32(const void* p) {
    u32 a;
    asm("{ .reg .u64 t; cvta.to.shared.u64 t, %1; cvt.u32.u64 %0, t; }" : "=r"(a) : "l"(p));
    return a;
}
__device__ __forceinline__ void cpa16s(u32 dst, const void* src) {
    asm volatile("cp.async.cg.shared.global [%0], [%1], 16;" :: "r"(dst), "l"(src));
}
#define CP_COMMIT() asm volatile("cp.async.commit_group;" ::: "memory")
#define CP_WAIT(n)  asm volatile("cp.async.wait_group %0;" :: "n"(n) : "memory")

#define LDSM4(r0, r1, r2, r3, a) \
    asm volatile("ldmatrix.sync.aligned.m8n8.x4.shared.b16 {%0,%1,%2,%3}, [%4];" \
                 : "=r"(r0), "=r"(r1), "=r"(r2), "=r"(r3) : "r"(a))

#define MMA16816(c, a, b) \
    asm volatile("mma.sync.aligned.m16n8k16.row.col.f32.bf16.bf16.f32 " \
                 "{%0,%1,%2,%3}, {%4,%5,%6,%7}, {%8,%9}, {%0,%1,%2,%3};" \
                 : "+f"((c)[0]), "+f"((c)[1]), "+f"((c)[2]), "+f"((c)[3]) \
                 : "r"((a)[0]), "r"((a)[1]), "r"((a)[2]), "r"((a)[3]), \
                   "r"((b)[0]), "r"((b)[1]))

// swizzled byte offset inside a 128x128B chunk tile
__device__ __forceinline__ u32 swoff(int r, int kb) {
    u32 off = ((u32)(r >> 3) << 10) + ((u32)(r & 7) << 7) + (u32)kb;
    return off ^ ((off >> 3) & 0x70);
}

// ---------------- transpose in/out -----------------------------------------
__global__ void k_transpose_in(const float* __restrict__ x) {
    __shared__ float tile[32][33];
    int n = blockIdx.z, t0 = blockIdx.x * 32, c0 = blockIdx.y * 32;
    const float* xin = x + (size_t)n * Cc * Tt;
#pragma unroll
    for (int k = 0; k < 4; k++)
        tile[threadIdx.y + k * 8][threadIdx.x] =
            xin[(size_t)(c0 + threadIdx.y + k * 8) * Tt + t0 + threadIdx.x];
    __syncthreads();
    float* xo = g_xt  + (size_t)n * Tt * Cc;
    float* ro = g_res + (size_t)n * Tt * Cc;
#pragma unroll
    for (int k = 0; k < 4; k++) {
        int t = t0 + threadIdx.y + k * 8;
        float v = tile[threadIdx.x][threadIdx.y + k * 8];
        size_t o = (size_t)t * Cc + c0 + threadIdx.x;
        xo[o] = v; ro[o] = v;
    }
}

__global__ void k_transpose_out(float* __restrict__ out) {
    __shared__ float tile[32][33];
    int n = blockIdx.z, c0 = blockIdx.x * 32, t0 = blockIdx.y * 32;
    const float* fi = g_fhat + (size_t)n * Tt * Cc;
#pragma unroll
    for (int k = 0; k < 4; k++)
        tile[threadIdx.y + k * 8][threadIdx.x] =
            fi[(size_t)(t0 + threadIdx.y + k * 8) * Cc + c0 + threadIdx.x];
    __syncthreads();
    float* oo = out + (size_t)n * Cc * Tt;
#pragma unroll
    for (int k = 0; k < 4; k++)
        oo[(size_t)(c0 + threadIdx.y + k * 8) * Tt + t0 + threadIdx.x] =
            tile[threadIdx.x][threadIdx.y + k * 8];
}

// ---------------- codebook half norms --------------------------------------
__global__ void k_cbhalf(const float* __restrict__ cb) {
    int k = blockIdx.x;
    const float* row = cb + (size_t)k * Cc;
    float s = 0.f;
    for (int i = threadIdx.x; i < Cc; i += 128) { float v = row[i]; s += v * v; }
#pragma unroll
    for (int o = 16; o; o >>= 1) s += __shfl_down_sync(0xffffffffu, s, o);
    __shared__ float ws[4];
    if ((threadIdx.x & 31) == 0) ws[threadIdx.x >> 5] = s;
    __syncthreads();
    if (threadIdx.x == 0) g_cbhalf[k] = 0.5f * (ws[0] + ws[1] + ws[2] + ws[3]);
}

// ---------------- exact 3-way bf16 split writers ----------------------------
// Layout per 128-row panel: [chunk(24)][SW128-swizzled 128x64 bf16 tile (16KB)]
// chunk = split*8 + kgroup/8
__device__ __forceinline__ void split_write(__nv_bfloat16* base, size_t panel,
                                            int r, int kg, const float* f) {
    union { __nv_bfloat16 b[8]; uint4 v; } H, M, L;
#pragma unroll
    for (int j = 0; j < 8; j++) {
        __nv_bfloat16 h = __float2bfloat16(f[j]);
        float mr = f[j] - __bfloat162float(h);
        __nv_bfloat16 m = __float2bfloat16(mr);
        float lr = mr - __bfloat162float(m);
        H.b[j] = h; M.b[j] = m; L.b[j] = __float2bfloat16(lr);
    }
    u32 sw = swoff(r, (kg & 7) << 4);
    char* pb = (char*)base + panel * PANEL_BYTES + sw;
    int cb0 = (kg >> 3) * CHUNK_BYTES;
    *(uint4*)(pb + cb0)                    = H.v;
    *(uint4*)(pb + cb0 + 8  * CHUNK_BYTES) = M.v;
    *(uint4*)(pb + cb0 + 16 * CHUNK_BYTES) = L.v;
}

__global__ void k_cb_split(const float* __restrict__ cb) {
    int panel = blockIdx.x;
    for (int it = 0; it < 32; it++) {
        int item = it * 256 + threadIdx.x;
        int r = item >> 6, kg = item & 63;
        const float4* s4 = (const float4*)(cb + ((size_t)(panel * 128 + r)) * Cc + kg * 8);
        float4 a = s4[0], b = s4[1];
        float f[8] = {a.x, a.y, a.z, a.w, b.x, b.y, b.z, b.w};
        split_write(g_cbS, panel, r, kg, f);
    }
}

__global__ void k_rd_split(const int* __restrict__ m_lens, int s, int t) {
    int panel = blockIdx.x;
    for (int it = 0; it < 32; it++) {
        int item = it * 256 + threadIdx.x;
        int r = item >> 6, kg = item & 63;
        int grow = panel * 128 + r;
        int n = grow / t, tp = grow % t;
        int ml = m_lens[n];
        float f[8] = {0.f, 0.f, 0.f, 0.f, 0.f, 0.f, 0.f, 0.f};
        for (int u = 0; u < s; u++) {
            if (tp * s + u < ml) {
                const float4* s4 =
                    (const float4*)(g_res + ((size_t)n * Tt + tp * s + u) * Cc + kg * 8);
                float4 a = s4[0], b = s4[1];
                f[0] += a.x; f[1] += a.y; f[2] += a.z; f[3] += a.w;
                f[4] += b.x; f[5] += b.y; f[6] += b.z; f[7] += b.w;
            }
        }
        float inv = 1.0f / (float)s;
#pragma unroll
        for (int j = 0; j < 8; j++) f[j] *= inv;
        split_write(g_rdS, panel, r, kg, f);
    }
}

// ---------------- scalar prep ----------------------------------------------
__global__ void k_prep_scalars(const int* __restrict__ m_lens) {
    __shared__ int sm[Nn];
    if (threadIdx.x < Nn) sm[threadIdx.x] = m_lens[threadIdx.x];
    __syncthreads();
    if (threadIdx.x == 0) {
        int s = 0;
        for (int i = 0; i < Nn; i++) s += sm[i];
        g_masksum = (float)s;
    }
    if (threadIdx.x < 3) g_err[threadIdx.x] = 0.0;
}
__global__ void k_reset_hist() { g_hist[blockIdx.x * 256 + threadIdx.x] = 0.f; }

// ---------------- quantize v5: mma.sync bf16, 6-term cross split ------------
// grid: (8 K-splits, panels). Block: 128 rows x 128 codes, 256 threads.
// Logical GEMM K' = 48 chunks; chunk i -> A split c_mapA[i/8], B split c_mapB[i/8].
__device__ __forceinline__ void fill_stage(u32 stage, const char* A,
                                           const char* B, int tid) {
#pragma unroll
    for (int q = 0; q < 4; q++) {
        int off = (tid + q * 256) * 16;
        cpa16s(stage + off, A + off);
    }
#pragma unroll
    for (int q = 0; q < 4; q++) {
        int off = (tid + q * 256) * 16;
        cpa16s(stage + CHUNK_BYTES + off, B + off);
    }
    CP_COMMIT();
}

__global__ void __launch_bounds__(256, 2)
k_quantize5(const int* __restrict__ m_lens, int t, int scale,
            float* __restrict__ pval, int* __restrict__ pidx) {
    extern __shared__ char dsm[];
    __shared__ float s_cbh[128];

    int tid = threadIdx.x, wid = tid >> 5, lane = tid & 31;
    int mbase = blockIdx.y * 128;
    int n = mbase / t;                       // t % 128 == 0
    int tlim = m_lens[n] / scale;
    if (mbase % t >= tlim) return;           // fully masked panel

    u32 dbase = (smem_u32(dsm) + 1023) & ~1023u;
    u32 st0 = dbase, st1 = dbase + 2 * CHUNK_BYTES;

    if (tid < 128) s_cbh[tid] = g_cbhalf[blockIdx.x * 128 + tid];

    const char* A = (const char*)g_rdS + (size_t)blockIdx.y * PANEL_BYTES;
    const char* B = (const char*)g_cbS + (size_t)blockIdx.x * PANEL_BYTES;

#define SRC_A(i) (A + (size_t)(c_mapA[(i) >> 3] * 8 + ((i) & 7)) * CHUNK_BYTES)
#define SRC_B(i) (B + (size_t)(c_mapB[(i) >> 3] * 8 + ((i) & 7)) * CHUNK_BYTES)

    fill_stage(st0, SRC_A(0), SRC_B(0), tid);
    fill_stage(st1, SRC_A(1), SRC_B(1), tid);

    int warp_m = wid >> 2, warp_n = wid & 3;
    int sub = lane >> 3;
    int a_row = warp_m * 64 + (lane & 7) + ((sub & 1) << 3);   // + mt*16
    int a_kb  = (sub >> 1) << 4;                               // + ks*32
    int b_row = warp_n * 32 + (lane & 7) + ((lane >> 4) << 3); // + pr*16
    int b_kb  = ((lane >> 3) & 1) << 4;                        // + ks*32

    float acc[4][4][4];
#pragma unroll
    for (int i = 0; i < 4; i++)
#pragma unroll
        for (int j = 0; j < 4; j++)
#pragma unroll
            for (int q = 0; q < 4; q++) acc[i][j][q] = 0.f;

    for (int i = 0; i < GCHUNK; i++) {
        if (i < GCHUNK - 1) CP_WAIT(1); else CP_WAIT(0);
        __syncthreads();
        u32 sa = (i & 1) ? st1 : st0;
        u32 sb = sa + CHUNK_BYTES;

#pragma unroll
        for (int ks = 0; ks < 4; ks++) {
            u32 af[4][4];
#pragma unroll
            for (int mt = 0; mt < 4; mt++) {
                u32 addr = sa + swoff(a_row + mt * 16, ks * 32 + a_kb);
                LDSM4(af[mt][0], af[mt][1], af[mt][2], af[mt][3], addr);
            }
            u32 bf[4][2];
#pragma unroll
            for (int pr = 0; pr < 2; pr++) {
                u32 addr = sb + swoff(b_row + pr * 16, ks * 32 + b_kb);
                LDSM4(bf[2 * pr][0], bf[2 * pr][1],
                      bf[2 * pr + 1][0], bf[2 * pr + 1][1], addr);
            }
#pragma unroll
            for (int mt = 0; mt < 4; mt++)
#pragma unroll
                for (int nt = 0; nt < 4; nt++)
                    MMA16816(acc[mt][nt], af[mt], bf[nt]);
        }
        __syncthreads();
        if (i + 2 < GCHUNK)
            fill_stage((i & 1) ? st1 : st0, SRC_A(i + 2), SRC_B(i + 2), tid);
    }

    // ---- epilogue: half-norm subtract + argmax ----
    float bv[8]; int bi[8];
#pragma unroll
    for (int s = 0; s < 8; s++) { bv[s] = -1e30f; bi[s] = 0; }

    int colq = (lane & 3) * 2;
#pragma unroll
    for (int mt = 0; mt < 4; mt++) {
#pragma unroll
        for (int nt = 0; nt < 4; nt++) {
            int cl = warp_n * 32 + nt * 8 + colq;
            int cg = blockIdx.x * 128 + cl;
            float h0 = s_cbh[cl], h1 = s_cbh[cl + 1];
            float v0 = acc[mt][nt][0] - h0;
            float v1 = acc[mt][nt][1] - h1;
            float v2 = acc[mt][nt][2] - h0;
            float v3 = acc[mt][nt][3] - h1;
            int lo = mt * 2, hi = mt * 2 + 1;
            if (v0 > bv[lo]) { bv[lo] = v0; bi[lo] = cg; }
            if (v1 > bv[lo]) { bv[lo] = v1; bi[lo] = cg + 1; }
            if (v2 > bv[hi]) { bv[hi] = v2; bi[hi] = cg; }
            if (v3 > bv[hi]) { bv[hi] = v3; bi[hi] = cg + 1; }
        }
    }
#pragma unroll
    for (int s = 0; s < 8; s++) {
#pragma unroll
        for (int o = 1; o <= 2; o <<= 1) {
            float ov = __shfl_xor_sync(0xffffffffu, bv[s], o);
            int   oi = __shfl_xor_sync(0xffffffffu, bi[s], o);
            if (ov > bv[s] || (ov == bv[s] && oi < bi[s])) { bv[s] = ov; bi[s] = oi; }
        }
    }

    __syncthreads();
    float* sval = (float*)dsm;             // [128][4]
    int*   sidx = (int*)(dsm + 2048);      // [128][4]
    if ((lane & 3) == 0) {
#pragma unroll
        for (int s = 0; s < 8; s++) {
            int row = warp_m * 64 + (s >> 1) * 16 + (lane >> 2) + (s & 1) * 8;
            sval[row * 4 + warp_n] = bv[s];
            sidx[row * 4 + warp_n] = bi[s];
        }
    }
    __syncthreads();
    if (tid < 128) {
        float b = sval[tid * 4]; int ix = sidx[tid * 4];
        for (int w = 1; w < 4; w++) {
            float v = sval[tid * 4 + w]; int ii = sidx[tid * 4 + w];
            if (v > b || (v == b && ii < ix)) { b = v; ix = ii; }
        }
        int grow = mbase + tid;
        pval[grow * 8 + blockIdx.x] = b;
        pidx[grow * 8 + blockIdx.x] = ix;
    }
#undef SRC_A
#undef SRC_B
}

// ---------------- combine K-split partials ---------------------------------
__global__ void k_argreduce(const float* __restrict__ pval, const int* __restrict__ pidx,
                            int* __restrict__ idx_out, int M) {
    int r = blockIdx.x * 256 + threadIdx.x;
    if (r >= M) return;
    float bv = pval[r * 8]; int bi = pidx[r * 8];
    for (int s = 1; s < 8; s++) {
        float v = pval[r * 8 + s]; int ii = pidx[r * 8 + s];
        if (v > bv || (v == bv && ii < bi)) { bv = v; bi = ii; }
    }
    idx_out[r] = bi;
}

// ---------------- masked histogram ------------------------------------------
__global__ void k_hist(const int* __restrict__ m_lens, int t, int scale,
                       const int* __restrict__ idxbuf, int M) {
    int r = blockIdx.x * 256 + threadIdx.x;
    if (r >= M) return;
    int n = r / t, tr = r % t;
    if (tr < m_lens[n] / scale) atomicAdd(&g_hist[idxbuf[r]], 1.0f);
}

// ---------------- upsample + residual/f_hat update + loss -------------------
__global__ void k_update(const float* __restrict__ cb,
                         const int* __restrict__ m_lens,
                         int s, int t, const int* __restrict__ idxbuf, int sid) {
    int g = blockIdx.x;
    int n = g / Tt, j = g % Tt;
    int ml = m_lens[n];
    int tlim = ml / s;
    float pos = (j + 0.5f) / (float)s - 0.5f;
    pos = fminf(fmaxf(pos, 0.0f), (float)(t - 1));
    int lo = (int)floorf(pos);
    int hi = min(lo + 1, t - 1);
    float w = pos - (float)lo;
    const int* idxn = idxbuf + n * t;
    int ilo = (lo < tlim) ? idxn[lo] : -1;
    int ihi = (hi < tlim) ? idxn[hi] : -1;
    float wl = 1.0f - w, wh = w;
    bool mask = (j < ml);
    float mm = mask ? 1.0f : 0.0f;

    size_t base = ((size_t)n * Tt + j) * (Cc / 4);
    float4* resp = ((float4*)g_res) + base;
    float4* fhp  = ((float4*)g_fhat) + base;
    const float4* xtp = ((const float4*)g_xt) + base;
    const float4* clo = (const float4*)(cb + (size_t)max(ilo, 0) * Cc);
    const float4* chi = (const float4*)(cb + (size_t)max(ihi, 0) * Cc);

    int i = threadIdx.x;
    float4 up = make_float4(0.f, 0.f, 0.f, 0.f);
    if (ilo >= 0) { float4 v = clo[i]; up.x += wl * v.x; up.y += wl * v.y; up.z += wl * v.z; up.w += wl * v.w; }
    if (ihi >= 0) { float4 v = chi[i]; up.x += wh * v.x; up.y += wh * v.y; up.z += wh * v.z; up.w += wh * v.w; }

    float4 r4 = resp[i];
    float4 rn = make_float4(r4.x * mm - up.x, r4.y * mm - up.y,
                            r4.z * mm - up.z, r4.w * mm - up.w);
    float4 f4 = fhp[i];
    float4 fn = make_float4(f4.x + up.x, f4.y + up.y, f4.z + up.z, f4.w + up.w);
    resp[i] = rn;
    fhp[i]  = fn;

    float lsum = 0.f;
    if (mask) {
        float4 xv = xtp[i];
        float ex = xv.x - fn.x, ey = xv.y - fn.y, ez = xv.z - fn.z, ew = xv.w - fn.w;
        lsum = ex * ex + ey * ey + ez * ez + ew * ew;
    }
#pragma unroll
    for (int o = 16; o; o >>= 1) lsum += __shfl_down_sync(0xffffffffu, lsum, o);
    __shared__ float ws[4];
    if ((threadIdx.x & 31) == 0) ws[threadIdx.x >> 5] = lsum;
    __syncthreads();
    if (threadIdx.x == 0 && mask)
        atomicAdd(&g_err[sid], (double)(ws[0] + ws[1] + ws[2] + ws[3]));
}

// ---------------- finalize ---------------------------------------------------
__global__ void k_finalize(float* __restrict__ out) {
    int tid = threadIdx.x;
    float c = g_hist[tid];
    __shared__ float ws[32];
    float v = c;
#pragma unroll
    for (int o = 16; o; o >>= 1) v += __shfl_down_sync(0xffffffffu, v, o);
    if ((tid & 31) == 0) ws[tid >> 5] = v;
    __syncthreads();
    if (tid < 32) {
        float z = ws[tid];
#pragma unroll
        for (int o = 16; o; o >>= 1) z += __shfl_down_sync(0xffffffffu, z, o);
        if (tid == 0) ws[0] = z;
    }
    __syncthreads();
    float total = ws[0];
    __syncthreads();
    float p = c / total;
    float e = p * logf(p + 1e-7f);
#pragma unroll
    for (int o = 16; o; o >>= 1) e += __shfl_down_sync(0xffffffffu, e, o);
    if ((tid & 31) == 0) ws[tid >> 5] = e;
    __syncthreads();
    if (tid == 0) {
        float ent = 0.f;
        for (int i = 0; i < 32; i++) ent += ws[i];
        double denom = (double)g_masksum * (double)Tt;
        double loss = (g_err[0] + g_err[1] + g_err[2]) / denom / 3.0;
        out[NCT]     = (float)loss;
        out[NCT + 1] = expf(-ent);
    }
}

// ---------------- launch ------------------------------------------------------
extern "C" void kernel_launch(void* const* d_in, const int* in_sizes, int n_in,
                              void* d_out, int out_size) {
    const float* x = nullptr; const float* cb = nullptr; const int* m_lens = nullptr;
    for (int i = 0; i < n_in; i++) {
        if (in_sizes[i] == NCT)            x = (const float*)d_in[i];
        else if (in_sizes[i] == Kk * Cc)   cb = (const float*)d_in[i];
        else if (in_sizes[i] == Nn)        m_lens = (const int*)d_in[i];
    }
    float* out = (float*)d_out;

    const int DYN = 1024 + 4 * CHUNK_BYTES;   // align pad + two 32KB stages
    cudaFuncSetAttribute(k_quantize5, cudaFuncAttributeMaxDynamicSharedMemorySize, DYN);

    void* fh = nullptr;   cudaGetSymbolAddress(&fh, g_fhat);
    cudaMemsetAsync(fh, 0, sizeof(float) * NCT, 0);
    void* idxv = nullptr; cudaGetSymbolAddress(&idxv, g_idx);
    int* idxbase = (int*)idxv;
    void* pvv = nullptr;  cudaGetSymbolAddress(&pvv, g_pval);
    float* pval = (float*)pvv;
    void* piv = nullptr;  cudaGetSymbolAddress(&piv, g_pidx);
    int* pidx = (int*)piv;

    k_reset_hist<<<4, 256>>>();
    k_prep_scalars<<<1, 64>>>(m_lens);
    k_cbhalf<<<Kk, 128>>>(cb);
    k_cb_split<<<8, 256>>>(cb);
    {
        dim3 gb(Tt / 32, Cc / 32, Nn), tb(32, 8);
        k_transpose_in<<<gb, tb>>>(x);
    }

    const int scales[3] = {4, 2, 1};
    const int offs[3]   = {0, Nn * 128, Nn * 128 + Nn * 256};
    for (int s = 0; s < 3; s++) {
        int sc = scales[s], t = Tt / sc, M = Nn * t;
        int panels = M / 128;
        int* idxp = idxbase + offs[s];
        k_rd_split<<<panels, 256>>>(m_lens, sc, t);
        k_quantize5<<<dim3(8, panels), 256, DYN>>>(m_lens, t, sc, pval, pidx);
        k_argreduce<<<(M + 255) / 256, 256>>>(pval, pidx, idxp, M);
        k_hist<<<(M + 255) / 256, 256>>>(m_lens, t, sc, idxp, M);
        k_update<<<Nn * Tt, 128>>>(cb, m_lens, sc, t, idxp, s);
    }

    k_finalize<<<1, 1024>>>(out);
    {
        dim3 gb(Cc / 32, Tt / 32, Nn), tb(32, 8);
        k_transpose_out<<<gb, tb>>>(out);
    }
}

// round 6
// speedup vs baseline: 4.3618x; 1.7359x over previous
#include <cuda_runtime.h>
#include <cuda_bf16.h>
#include <math.h>

#define Nn 64
#define Cc 512
#define Tt 512
#define Kk 1024
#define NCT (Nn*Cc*Tt)

#define GCHUNK 8                // K' = 512 bf16 (h.h only) = 8 chunks of 64
#define CHUNK_BYTES 16384       // 128 rows x 64 bf16 (SW128-swizzled)
#define PANEL_BYTES (GCHUNK*CHUNK_BYTES)   // 128 KB
#define PANEL_ELEMS (GCHUNK*8192)

typedef unsigned int u32;
typedef unsigned long long u64;

// ---------------- device scratch ------------------------------------------
__device__ float  g_xt[NCT];
__device__ float  g_res[NCT];
__device__ float  g_fhat[NCT];
__device__ float  g_rd[32768 * Cc];                      // pooled rows fp32
__device__ float  g_score[32768 * Kk];                   // pass-1 scores
__device__ __align__(16) __nv_bfloat16 g_rdS[256 * PANEL_ELEMS]; // h split A
__device__ __align__(16) __nv_bfloat16 g_cbS[8   * PANEL_ELEMS]; // h split B
__device__ int    g_idx[Nn*(128+256+512)];
__device__ float  g_cbhalf[Kk];
__device__ float  g_hn[32768];   // ||h_x|| per row
__device__ float  g_ex[32768];   // ||x - h_x|| per row
__device__ float  g_Hy, g_Ey;    // max ||h_k||, max ||cb_k - h_k||
__device__ float  g_hist[Kk];
__device__ double g_err[3];
__device__ float  g_masksum;

// ---------------- PTX helpers ---------------------------------------------
__device__ __forceinline__ u32 smem_u32(const void* p) {
    u32 a;
    asm("{ .reg .u64 t; cvta.to.shared.u64 t, %1; cvt.u32.u64 %0, t; }" : "=r"(a) : "l"(p));
    return a;
}
__device__ __forceinline__ void cpa16s(u32 dst, const void* src) {
    asm volatile("cp.async.cg.shared.global [%0], [%1], 16;" :: "r"(dst), "l"(src));
}
#define CP_COMMIT() asm volatile("cp.async.commit_group;" ::: "memory")
#define CP_WAIT(n)  asm volatile("cp.async.wait_group %0;" :: "n"(n) : "memory")

#define LDSM4(r0, r1, r2, r3, a) \
    asm volatile("ldmatrix.sync.aligned.m8n8.x4.shared.b16 {%0,%1,%2,%3}, [%4];" \
                 : "=r"(r0), "=r"(r1), "=r"(r2), "=r"(r3) : "r"(a))

#define MMA16816(c, a, b) \
    asm volatile("mma.sync.aligned.m16n8k16.row.col.f32.bf16.bf16.f32 " \
                 "{%0,%1,%2,%3}, {%4,%5,%6,%7}, {%8,%9}, {%0,%1,%2,%3};" \
                 : "+f"((c)[0]), "+f"((c)[1]), "+f"((c)[2]), "+f"((c)[3]) \
                 : "r"((a)[0]), "r"((a)[1]), "r"((a)[2]), "r"((a)[3]), \
                   "r"((b)[0]), "r"((b)[1]))

__device__ __forceinline__ u32 swoff(int r, int kb) {
    u32 off = ((u32)(r >> 3) << 10) + ((u32)(r & 7) << 7) + (u32)kb;
    return off ^ ((off >> 3) & 0x70);
}
__device__ __forceinline__ void atomicMaxF(float* a, float v) {
    atomicMax((int*)a, __float_as_int(v));   // valid: values >= 0
}

// ---------------- transpose in/out -----------------------------------------
__global__ void k_transpose_in(const float* __restrict__ x) {
    __shared__ float tile[32][33];
    int n = blockIdx.z, t0 = blockIdx.x * 32, c0 = blockIdx.y * 32;
    const float* xin = x + (size_t)n * Cc * Tt;
#pragma unroll
    for (int k = 0; k < 4; k++)
        tile[threadIdx.y + k * 8][threadIdx.x] =
            xin[(size_t)(c0 + threadIdx.y + k * 8) * Tt + t0 + threadIdx.x];
    __syncthreads();
    float* xo = g_xt  + (size_t)n * Tt * Cc;
    float* ro = g_res + (size_t)n * Tt * Cc;
#pragma unroll
    for (int k = 0; k < 4; k++) {
        int t = t0 + threadIdx.y + k * 8;
        float v = tile[threadIdx.x][threadIdx.y + k * 8];
        size_t o = (size_t)t * Cc + c0 + threadIdx.x;
        xo[o] = v; ro[o] = v;
    }
}

__global__ void k_transpose_out(float* __restrict__ out) {
    __shared__ float tile[32][33];
    int n = blockIdx.z, c0 = blockIdx.x * 32, t0 = blockIdx.y * 32;
    const float* fi = g_fhat + (size_t)n * Tt * Cc;
#pragma unroll
    for (int k = 0; k < 4; k++)
        tile[threadIdx.y + k * 8][threadIdx.x] =
            fi[(size_t)(t0 + threadIdx.y + k * 8) * Cc + c0 + threadIdx.x];
    __syncthreads();
    float* oo = out + (size_t)n * Cc * Tt;
#pragma unroll
    for (int k = 0; k < 4; k++)
        oo[(size_t)(c0 + threadIdx.y + k * 8) * Tt + t0 + threadIdx.x] =
            tile[threadIdx.x][threadIdx.y + k * 8];
}

// ------- codebook: half norms + bound constants ----------------------------
__global__ void k_cbhalf(const float* __restrict__ cb) {
    int k = blockIdx.x;
    const float* row = cb + (size_t)k * Cc;
    float s = 0.f, h2 = 0.f, e2 = 0.f;
    for (int i = threadIdx.x; i < Cc; i += 128) {
        float v = row[i];
        float hf = __bfloat162float(__float2bfloat16(v));
        float d = v - hf;
        s += v * v; h2 += hf * hf; e2 += d * d;
    }
#pragma unroll
    for (int o = 16; o; o >>= 1) {
        s  += __shfl_down_sync(0xffffffffu, s,  o);
        h2 += __shfl_down_sync(0xffffffffu, h2, o);
        e2 += __shfl_down_sync(0xffffffffu, e2, o);
    }
    __shared__ float ws[4], wh[4], we[4];
    if ((threadIdx.x & 31) == 0) {
        ws[threadIdx.x >> 5] = s; wh[threadIdx.x >> 5] = h2; we[threadIdx.x >> 5] = e2;
    }
    __syncthreads();
    if (threadIdx.x == 0) {
        float S = ws[0] + ws[1] + ws[2] + ws[3];
        float H = wh[0] + wh[1] + wh[2] + wh[3];
        float E = we[0] + we[1] + we[2] + we[3];
        g_cbhalf[k] = 0.5f * S;
        atomicMaxF(&g_Hy, sqrtf(H));
        atomicMaxF(&g_Ey, sqrtf(E));
    }
}

// ---------------- codebook h-split panels -----------------------------------
__global__ void k_cb_split(const float* __restrict__ cb) {
    int panel = blockIdx.x;
    for (int it = 0; it < 32; it++) {
        int item = it * 256 + threadIdx.x;
        int r = item >> 6, kg = item & 63;
        const float4* s4 = (const float4*)(cb + ((size_t)(panel * 128 + r)) * Cc + kg * 8);
        float4 a = s4[0], b = s4[1];
        float f[8] = {a.x, a.y, a.z, a.w, b.x, b.y, b.z, b.w};
        union { __nv_bfloat16 bb[8]; uint4 v; } H;
#pragma unroll
        for (int j = 0; j < 8; j++) H.bb[j] = __float2bfloat16(f[j]);
        u32 sw = swoff(r, (kg & 7) << 4);
        char* pb = (char*)g_cbS + (size_t)panel * PANEL_BYTES
                 + (size_t)(kg >> 3) * CHUNK_BYTES + sw;
        *(uint4*)pb = H.v;
    }
}

// ------- mask + avg-pool residual: fp32 rows + h panels + row norms ---------
__global__ void k_rd_split(const int* __restrict__ m_lens, int s, int t) {
    __shared__ float s_h2[128], s_e2[128];
    int tid = threadIdx.x, panel = blockIdx.x;
    if (tid < 128) { s_h2[tid] = 0.f; s_e2[tid] = 0.f; }
    __syncthreads();
    float inv = 1.0f / (float)s;
    for (int it = 0; it < 32; it++) {
        int item = it * 256 + tid;
        int r = item >> 6, kg = item & 63;
        int grow = panel * 128 + r;
        int n = grow / t, tp = grow % t;
        int ml = m_lens[n];
        float f[8] = {0.f, 0.f, 0.f, 0.f, 0.f, 0.f, 0.f, 0.f};
        for (int u = 0; u < s; u++) {
            if (tp * s + u < ml) {
                const float4* s4 =
                    (const float4*)(g_res + ((size_t)n * Tt + tp * s + u) * Cc + kg * 8);
                float4 a = s4[0], b = s4[1];
                f[0] += a.x; f[1] += a.y; f[2] += a.z; f[3] += a.w;
                f[4] += b.x; f[5] += b.y; f[6] += b.z; f[7] += b.w;
            }
        }
#pragma unroll
        for (int j = 0; j < 8; j++) f[j] *= inv;
        // fp32 pooled row
        float4* rp = (float4*)(g_rd + (size_t)grow * Cc + kg * 8);
        rp[0] = make_float4(f[0], f[1], f[2], f[3]);
        rp[1] = make_float4(f[4], f[5], f[6], f[7]);
        // h split + norm partials
        union { __nv_bfloat16 bb[8]; uint4 v; } H;
        float h2 = 0.f, e2 = 0.f;
#pragma unroll
        for (int j = 0; j < 8; j++) {
            __nv_bfloat16 h = __float2bfloat16(f[j]);
            float hf = __bfloat162float(h);
            float d = f[j] - hf;
            H.bb[j] = h; h2 += hf * hf; e2 += d * d;
        }
        u32 sw = swoff(r, (kg & 7) << 4);
        char* pb = (char*)g_rdS + (size_t)panel * PANEL_BYTES
                 + (size_t)(kg >> 3) * CHUNK_BYTES + sw;
        *(uint4*)pb = H.v;
#pragma unroll
        for (int o = 16; o; o >>= 1) {
            h2 += __shfl_down_sync(0xffffffffu, h2, o);
            e2 += __shfl_down_sync(0xffffffffu, e2, o);
        }
        if ((tid & 31) == 0) {
            atomicAdd(&s_h2[r], h2);
            atomicAdd(&s_e2[r], e2);
        }
    }
    __syncthreads();
    if (tid < 128) {
        g_hn[panel * 128 + tid] = sqrtf(s_h2[tid]);
        g_ex[panel * 128 + tid] = sqrtf(s_e2[tid]);
    }
}

// ---------------- scalar prep ----------------------------------------------
__global__ void k_prep_scalars(const int* __restrict__ m_lens) {
    __shared__ int sm[Nn];
    if (threadIdx.x < Nn) sm[threadIdx.x] = m_lens[threadIdx.x];
    __syncthreads();
    if (threadIdx.x == 0) {
        int s = 0;
        for (int i = 0; i < Nn; i++) s += sm[i];
        g_masksum = (float)s;
        g_Hy = 0.f; g_Ey = 0.f;
    }
    if (threadIdx.x < 3) g_err[threadIdx.x] = 0.0;
}
__global__ void k_reset_hist() { g_hist[blockIdx.x * 256 + threadIdx.x] = 0.f; }

// ---------------- pass 1: h.h GEMM -> scores ---------------------------------
__device__ __forceinline__ void fill_stage(u32 stage, const char* A,
                                           const char* B, int tid) {
#pragma unroll
    for (int q = 0; q < 4; q++) {
        int off = (tid + q * 256) * 16;
        cpa16s(stage + off, A + off);
    }
#pragma unroll
    for (int q = 0; q < 4; q++) {
        int off = (tid + q * 256) * 16;
        cpa16s(stage + CHUNK_BYTES + off, B + off);
    }
    CP_COMMIT();
}

__global__ void __launch_bounds__(256, 2)
k_quantize6(const int* __restrict__ m_lens, int t, int scale,
            float* __restrict__ score) {
    extern __shared__ char dsm[];
    __shared__ float s_cbh[128];

    int tid = threadIdx.x, wid = tid >> 5, lane = tid & 31;
    int mbase = blockIdx.y * 128;
    int n = mbase / t;
    int tlim = m_lens[n] / scale;
    if (mbase % t >= tlim) return;           // fully masked panel

    u32 dbase = (smem_u32(dsm) + 1023) & ~1023u;
    u32 st0 = dbase, st1 = dbase + 2 * CHUNK_BYTES;

    if (tid < 128) s_cbh[tid] = g_cbhalf[blockIdx.x * 128 + tid];

    const char* A = (const char*)g_rdS + (size_t)blockIdx.y * PANEL_BYTES;
    const char* B = (const char*)g_cbS + (size_t)blockIdx.x * PANEL_BYTES;

    fill_stage(st0, A, B, tid);
    fill_stage(st1, A + CHUNK_BYTES, B + CHUNK_BYTES, tid);

    int warp_m = wid >> 2, warp_n = wid & 3;
    int sub = lane >> 3;
    int a_row = warp_m * 64 + (lane & 7) + ((sub & 1) << 3);
    int a_kb  = (sub >> 1) << 4;
    int b_row = warp_n * 32 + (lane & 7) + ((lane >> 4) << 3);
    int b_kb  = ((lane >> 3) & 1) << 4;

    float acc[4][4][4];
#pragma unroll
    for (int i = 0; i < 4; i++)
#pragma unroll
        for (int j = 0; j < 4; j++)
#pragma unroll
            for (int q = 0; q < 4; q++) acc[i][j][q] = 0.f;

    for (int i = 0; i < GCHUNK; i++) {
        if (i < GCHUNK - 1) CP_WAIT(1); else CP_WAIT(0);
        __syncthreads();
        u32 sa = (i & 1) ? st1 : st0;
        u32 sb = sa + CHUNK_BYTES;
#pragma unroll
        for (int ks = 0; ks < 4; ks++) {
            u32 af[4][4];
#pragma unroll
            for (int mt = 0; mt < 4; mt++) {
                u32 addr = sa + swoff(a_row + mt * 16, ks * 32 + a_kb);
                LDSM4(af[mt][0], af[mt][1], af[mt][2], af[mt][3], addr);
            }
            u32 bf[4][2];
#pragma unroll
            for (int pr = 0; pr < 2; pr++) {
                u32 addr = sb + swoff(b_row + pr * 16, ks * 32 + b_kb);
                LDSM4(bf[2 * pr][0], bf[2 * pr][1],
                      bf[2 * pr + 1][0], bf[2 * pr + 1][1], addr);
            }
#pragma unroll
            for (int mt = 0; mt < 4; mt++)
#pragma unroll
                for (int nt = 0; nt < 4; nt++)
                    MMA16816(acc[mt][nt], af[mt], bf[nt]);
        }
        __syncthreads();
        if (i + 2 < GCHUNK)
            fill_stage((i & 1) ? st1 : st0,
                       A + (size_t)(i + 2) * CHUNK_BYTES,
                       B + (size_t)(i + 2) * CHUNK_BYTES, tid);
    }

    // ---- epilogue: subtract half-norm, store scores ----
    int r0 = warp_m * 64 + (lane >> 2);
    int cbase = warp_n * 32 + (lane & 3) * 2;
#pragma unroll
    for (int mt = 0; mt < 4; mt++) {
#pragma unroll
        for (int nt = 0; nt < 4; nt++) {
            int cl = cbase + nt * 8;
            float h0 = s_cbh[cl], h1 = s_cbh[cl + 1];
            size_t coff = (size_t)blockIdx.x * 128 + cl;
            int grow0 = mbase + r0 + mt * 16;
            float2* o0 = (float2*)(score + (size_t)grow0 * Kk + coff);
            *o0 = make_float2(acc[mt][nt][0] - h0, acc[mt][nt][1] - h1);
            float2* o1 = (float2*)(score + (size_t)(grow0 + 8) * Kk + coff);
            *o1 = make_float2(acc[mt][nt][2] - h0, acc[mt][nt][3] - h1);
        }
    }
}

// ---------------- rescore: prune + exact fp32 argmax + hist ------------------
__global__ void k_rescore(const float* __restrict__ cb,
                          const int* __restrict__ m_lens,
                          int t, int scale, int* __restrict__ idx_out) {
    int wid = threadIdx.x >> 5, lane = threadIdx.x & 31;
    int row = blockIdx.x * 8 + wid;
    int n = row / t, tr = row % t;
    int tlim = m_lens[n] / scale;
    if (tr >= tlim) {                        // masked row: idx unused downstream
        if (lane == 0) idx_out[row] = 0;
        return;
    }

    float xr[16];
    const float* xrp = g_rd + (size_t)row * Cc;
#pragma unroll
    for (int c = 0; c < 16; c++) xr[c] = xrp[c * 32 + lane];

    float sc[32];
    const float* sp = g_score + (size_t)row * Kk;
#pragma unroll
    for (int j = 0; j < 32; j++) sc[j] = sp[j * 32 + lane];

    float mx = -1e30f;
#pragma unroll
    for (int j = 0; j < 32; j++) mx = fmaxf(mx, sc[j]);
#pragma unroll
    for (int o = 16; o; o >>= 1) mx = fmaxf(mx, __shfl_xor_sync(0xffffffffu, mx, o));

    float B = 1.02f * (g_hn[row] * g_Ey + g_ex[row] * (g_Hy + g_Ey)) + 1e-2f;
    float tau = mx - 2.0f * B;

    float best = -1e30f; int bi = 0;
    for (int j = 0; j < 32; j++) {
        unsigned m = __ballot_sync(0xffffffffu, sc[j] >= tau);
        while (m) {
            int l = __ffs(m) - 1; m &= m - 1;
            int k = j * 32 + l;
            const float* cbk = cb + (size_t)k * Cc;
            float p = 0.f;
#pragma unroll
            for (int c = 0; c < 16; c++) p = fmaf(xr[c], cbk[c * 32 + lane], p);
#pragma unroll
            for (int o = 16; o; o >>= 1) p += __shfl_xor_sync(0xffffffffu, p, o);
            float sv = p - g_cbhalf[k];
            if (sv > best) { best = sv; bi = k; }   // ascending k: first max wins
        }
    }
    if (lane == 0) {
        idx_out[row] = bi;
        atomicAdd(&g_hist[bi], 1.0f);               // row is live here
    }
}

// ---------------- upsample + residual/f_hat update + loss -------------------
__global__ void k_update(const float* __restrict__ cb,
                         const int* __restrict__ m_lens,
                         int s, int t, const int* __restrict__ idxbuf, int sid) {
    int g = blockIdx.x;
    int n = g / Tt, j = g % Tt;
    int ml = m_lens[n];
    int tlim = ml / s;
    float pos = (j + 0.5f) / (float)s - 0.5f;
    pos = fminf(fmaxf(pos, 0.0f), (float)(t - 1));
    int lo = (int)floorf(pos);
    int hi = min(lo + 1, t - 1);
    float w = pos - (float)lo;
    const int* idxn = idxbuf + n * t;
    int ilo = (lo < tlim) ? idxn[lo] : -1;
    int ihi = (hi < tlim) ? idxn[hi] : -1;
    float wl = 1.0f - w, wh = w;
    bool mask = (j < ml);
    float mm = mask ? 1.0f : 0.0f;

    size_t base = ((size_t)n * Tt + j) * (Cc / 4);
    float4* resp = ((float4*)g_res) + base;
    float4* fhp  = ((float4*)g_fhat) + base;
    const float4* xtp = ((const float4*)g_xt) + base;
    const float4* clo = (const float4*)(cb + (size_t)max(ilo, 0) * Cc);
    const float4* chi = (const float4*)(cb + (size_t)max(ihi, 0) * Cc);

    int i = threadIdx.x;
    float4 up = make_float4(0.f, 0.f, 0.f, 0.f);
    if (ilo >= 0) { float4 v = clo[i]; up.x += wl * v.x; up.y += wl * v.y; up.z += wl * v.z; up.w += wl * v.w; }
    if (ihi >= 0) { float4 v = chi[i]; up.x += wh * v.x; up.y += wh * v.y; up.z += wh * v.z; up.w += wh * v.w; }

    float4 r4 = resp[i];
    float4 rn = make_float4(r4.x * mm - up.x, r4.y * mm - up.y,
                            r4.z * mm - up.z, r4.w * mm - up.w);
    float4 f4 = fhp[i];
    float4 fn = make_float4(f4.x + up.x, f4.y + up.y, f4.z + up.z, f4.w + up.w);
    resp[i] = rn;
    fhp[i]  = fn;

    float lsum = 0.f;
    if (mask) {
        float4 xv = xtp[i];
        float ex = xv.x - fn.x, ey = xv.y - fn.y, ez = xv.z - fn.z, ew = xv.w - fn.w;
        lsum = ex * ex + ey * ey + ez * ez + ew * ew;
    }
#pragma unroll
    for (int o = 16; o; o >>= 1) lsum += __shfl_down_sync(0xffffffffu, lsum, o);
    __shared__ float ws[4];
    if ((threadIdx.x & 31) == 0) ws[threadIdx.x >> 5] = lsum;
    __syncthreads();
    if (threadIdx.x == 0 && mask)
        atomicAdd(&g_err[sid], (double)(ws[0] + ws[1] + ws[2] + ws[3]));
}

// ---------------- finalize ---------------------------------------------------
__global__ void k_finalize(float* __restrict__ out) {
    int tid = threadIdx.x;
    float c = g_hist[tid];
    __shared__ float ws[32];
    float v = c;
#pragma unroll
    for (int o = 16; o; o >>= 1) v += __shfl_down_sync(0xffffffffu, v, o);
    if ((tid & 31) == 0) ws[tid >> 5] = v;
    __syncthreads();
    if (tid < 32) {
        float z = ws[tid];
#pragma unroll
        for (int o = 16; o; o >>= 1) z += __shfl_down_sync(0xffffffffu, z, o);
        if (tid == 0) ws[0] = z;
    }
    __syncthreads();
    float total = ws[0];
    __syncthreads();
    float p = c / total;
    float e = p * logf(p + 1e-7f);
#pragma unroll
    for (int o = 16; o; o >>= 1) e += __shfl_down_sync(0xffffffffu, e, o);
    if ((tid & 31) == 0) ws[tid >> 5] = e;
    __syncthreads();
    if (tid == 0) {
        float ent = 0.f;
        for (int i = 0; i < 32; i++) ent += ws[i];
        double denom = (double)g_masksum * (double)Tt;
        double loss = (g_err[0] + g_err[1] + g_err[2]) / denom / 3.0;
        out[NCT]     = (float)loss;
        out[NCT + 1] = expf(-ent);
    }
}

// ---------------- launch ------------------------------------------------------
extern "C" void kernel_launch(void* const* d_in, const int* in_sizes, int n_in,
                              void* d_out, int out_size) {
    const float* x = nullptr; const float* cb = nullptr; const int* m_lens = nullptr;
    for (int i = 0; i < n_in; i++) {
        if (in_sizes[i] == NCT)            x = (const float*)d_in[i];
        else if (in_sizes[i] == Kk * Cc)   cb = (const float*)d_in[i];
        else if (in_sizes[i] == Nn)        m_lens = (const int*)d_in[i];
    }
    float* out = (float*)d_out;

    const int DYN = 1024 + 4 * CHUNK_BYTES;
    cudaFuncSetAttribute(k_quantize6, cudaFuncAttributeMaxDynamicSharedMemorySize, DYN);

    void* fh = nullptr;   cudaGetSymbolAddress(&fh, g_fhat);
    cudaMemsetAsync(fh, 0, sizeof(float) * NCT, 0);
    void* idxv = nullptr; cudaGetSymbolAddress(&idxv, g_idx);
    int* idxbase = (int*)idxv;
    void* scv = nullptr;  cudaGetSymbolAddress(&scv, g_score);
    float* score = (float*)scv;

    k_reset_hist<<<4, 256>>>();
    k_prep_scalars<<<1, 64>>>(m_lens);
    k_cbhalf<<<Kk, 128>>>(cb);
    k_cb_split<<<8, 256>>>(cb);
    {
        dim3 gb(Tt / 32, Cc / 32, Nn), tb(32, 8);
        k_transpose_in<<<gb, tb>>>(x);
    }

    const int scales[3] = {4, 2, 1};
    const int offs[3]   = {0, Nn * 128, Nn * 128 + Nn * 256};
    for (int s = 0; s < 3; s++) {
        int sc = scales[s], t = Tt / sc, M = Nn * t;
        int panels = M / 128;
        int* idxp = idxbase + offs[s];
        k_rd_split<<<panels, 256>>>(m_lens, sc, t);
        k_quantize6<<<dim3(8, panels), 256, DYN>>>(m_lens, t, sc, score);
        k_rescore<<<M / 8, 256>>>(cb, m_lens, t, sc, idxp);
        k_update<<<Nn * Tt, 128>>>(cb, m_lens, sc, t, idxp, s);
    }

    k_finalize<<<1, 1024>>>(out);
    {
        dim3 gb(Cc / 32, Tt / 32, Nn), tb(32, 8);
        k_transpose_out<<<gb, tb>>>(out);
    }
}

// round 7
// speedup vs baseline: 5.1585x; 1.1827x over previous
#include <cuda_runtime.h>
#include <cuda_bf16.h>
#include <math.h>

#define Nn 64
#define Cc 512
#define Tt 512
#define Kk 1024
#define NCT (Nn*Cc*Tt)

#define GCHUNK 8                // K' = 512 bf16 (h.h only) = 8 chunks of 64
#define CHUNK_BYTES 16384       // 128 rows x 64 bf16 (SW128-swizzled)
#define PANEL_BYTES (GCHUNK*CHUNK_BYTES)   // 128 KB
#define PANEL_ELEMS (GCHUNK*8192)

typedef unsigned int u32;
typedef unsigned long long u64;

// ---------------- device scratch ------------------------------------------
__device__ float  g_xt[NCT];                             // x in (N,T,C)
__device__ float  g_fhat[NCT];                           // f_hat (N,T,C)
__device__ float  g_rd[32768 * Cc];                      // pooled rows fp32
__device__ float  g_score[32768 * Kk];                   // pass-1 scores
__device__ __align__(16) __nv_bfloat16 g_rdS[256 * PANEL_ELEMS]; // h split A
__device__ __align__(16) __nv_bfloat16 g_cbS[8   * PANEL_ELEMS]; // h split B
__device__ int    g_idx[Nn*(128+256+512)];
__device__ float  g_cbhalf[Kk];
__device__ float  g_hn[32768];   // ||h_x|| per row
__device__ float  g_ex[32768];   // ||x - h_x|| per row
__device__ float  g_Hy, g_Ey;    // max ||h_k||, max ||cb_k - h_k||
__device__ float  g_hist[Kk];
__device__ double g_err[3];
__device__ float  g_masksum;

// ---------------- PTX helpers ---------------------------------------------
__device__ __forceinline__ u32 smem_u32(const void* p) {
    u32 a;
    asm("{ .reg .u64 t; cvta.to.shared.u64 t, %1; cvt.u32.u64 %0, t; }" : "=r"(a) : "l"(p));
    return a;
}
__device__ __forceinline__ void cpa16s(u32 dst, const void* src) {
    asm volatile("cp.async.cg.shared.global [%0], [%1], 16;" :: "r"(dst), "l"(src));
}
#define CP_COMMIT() asm volatile("cp.async.commit_group;" ::: "memory")
#define CP_WAIT(n)  asm volatile("cp.async.wait_group %0;" :: "n"(n) : "memory")

#define LDSM4(r0, r1, r2, r3, a) \
    asm volatile("ldmatrix.sync.aligned.m8n8.x4.shared.b16 {%0,%1,%2,%3}, [%4];" \
                 : "=r"(r0), "=r"(r1), "=r"(r2), "=r"(r3) : "r"(a))

#define MMA16816(c, a, b) \
    asm volatile("mma.sync.aligned.m16n8k16.row.col.f32.bf16.bf16.f32 " \
                 "{%0,%1,%2,%3}, {%4,%5,%6,%7}, {%8,%9}, {%0,%1,%2,%3};" \
                 : "+f"((c)[0]), "+f"((c)[1]), "+f"((c)[2]), "+f"((c)[3]) \
                 : "r"((a)[0]), "r"((a)[1]), "r"((a)[2]), "r"((a)[3]), \
                   "r"((b)[0]), "r"((b)[1]))

__device__ __forceinline__ u32 swoff(int r, int kb) {
    u32 off = ((u32)(r >> 3) << 10) + ((u32)(r & 7) << 7) + (u32)kb;
    return off ^ ((off >> 3) & 0x70);
}
__device__ __forceinline__ void atomicMaxF(float* a, float v) {
    atomicMax((int*)a, __float_as_int(v));   // valid: values >= 0
}

// ---------------- transpose in: x (N,C,T) -> g_xt (N,T,C) -------------------
__global__ void k_transpose_in(const float* __restrict__ x) {
    __shared__ float tile[32][33];
    int n = blockIdx.z, t0 = blockIdx.x * 32, c0 = blockIdx.y * 32;
    const float* xin = x + (size_t)n * Cc * Tt;
#pragma unroll
    for (int k = 0; k < 4; k++)
        tile[threadIdx.y + k * 8][threadIdx.x] =
            xin[(size_t)(c0 + threadIdx.y + k * 8) * Tt + t0 + threadIdx.x];
    __syncthreads();
    float* xo = g_xt + (size_t)n * Tt * Cc;
#pragma unroll
    for (int k = 0; k < 4; k++) {
        int t = t0 + threadIdx.y + k * 8;
        xo[(size_t)t * Cc + c0 + threadIdx.x] = tile[threadIdx.x][threadIdx.y + k * 8];
    }
}

__global__ void k_transpose_out(float* __restrict__ out) {
    __shared__ float tile[32][33];
    int n = blockIdx.z, c0 = blockIdx.x * 32, t0 = blockIdx.y * 32;
    const float* fi = g_fhat + (size_t)n * Tt * Cc;
#pragma unroll
    for (int k = 0; k < 4; k++)
        tile[threadIdx.y + k * 8][threadIdx.x] =
            fi[(size_t)(t0 + threadIdx.y + k * 8) * Cc + c0 + threadIdx.x];
    __syncthreads();
    float* oo = out + (size_t)n * Cc * Tt;
#pragma unroll
    for (int k = 0; k < 4; k++)
        oo[(size_t)(c0 + threadIdx.y + k * 8) * Tt + t0 + threadIdx.x] =
            tile[threadIdx.x][threadIdx.y + k * 8];
}

// ------- codebook: half norms + bound constants ----------------------------
__global__ void k_cbhalf(const float* __restrict__ cb) {
    int k = blockIdx.x;
    const float* row = cb + (size_t)k * Cc;
    float s = 0.f, h2 = 0.f, e2 = 0.f;
    for (int i = threadIdx.x; i < Cc; i += 128) {
        float v = row[i];
        float hf = __bfloat162float(__float2bfloat16(v));
        float d = v - hf;
        s += v * v; h2 += hf * hf; e2 += d * d;
    }
#pragma unroll
    for (int o = 16; o; o >>= 1) {
        s  += __shfl_down_sync(0xffffffffu, s,  o);
        h2 += __shfl_down_sync(0xffffffffu, h2, o);
        e2 += __shfl_down_sync(0xffffffffu, e2, o);
    }
    __shared__ float ws[4], wh[4], we[4];
    if ((threadIdx.x & 31) == 0) {
        ws[threadIdx.x >> 5] = s; wh[threadIdx.x >> 5] = h2; we[threadIdx.x >> 5] = e2;
    }
    __syncthreads();
    if (threadIdx.x == 0) {
        float S = ws[0] + ws[1] + ws[2] + ws[3];
        float H = wh[0] + wh[1] + wh[2] + wh[3];
        float E = we[0] + we[1] + we[2] + we[3];
        g_cbhalf[k] = 0.5f * S;
        atomicMaxF(&g_Hy, sqrtf(H));
        atomicMaxF(&g_Ey, sqrtf(E));
    }
}

// ---------------- codebook h-split panels -----------------------------------
__global__ void k_cb_split(const float* __restrict__ cb) {
    int panel = blockIdx.x;
    for (int it = 0; it < 32; it++) {
        int item = it * 256 + threadIdx.x;
        int r = item >> 6, kg = item & 63;
        const float4* s4 = (const float4*)(cb + ((size_t)(panel * 128 + r)) * Cc + kg * 8);
        float4 a = s4[0], b = s4[1];
        float f[8] = {a.x, a.y, a.z, a.w, b.x, b.y, b.z, b.w};
        union { __nv_bfloat16 bb[8]; uint4 v; } H;
#pragma unroll
        for (int j = 0; j < 8; j++) H.bb[j] = __float2bfloat16(f[j]);
        u32 sw = swoff(r, (kg & 7) << 4);
        char* pb = (char*)g_cbS + (size_t)panel * PANEL_BYTES
                 + (size_t)(kg >> 3) * CHUNK_BYTES + sw;
        *(uint4*)pb = H.v;
    }
}

// ---------------- scalar prep ----------------------------------------------
__global__ void k_prep_scalars(const int* __restrict__ m_lens) {
    __shared__ int sm[Nn];
    if (threadIdx.x < Nn) sm[threadIdx.x] = m_lens[threadIdx.x];
    __syncthreads();
    if (threadIdx.x == 0) {
        int s = 0;
        for (int i = 0; i < Nn; i++) s += sm[i];
        g_masksum = (float)s;
        g_Hy = 0.f; g_Ey = 0.f;
    }
    if (threadIdx.x < 3) g_err[threadIdx.x] = 0.0;
}
__global__ void k_reset_hist() { g_hist[blockIdx.x * 256 + threadIdx.x] = 0.f; }

// ------- upsample helper: subtract up(j) for 8 channels ----------------------
__device__ __forceinline__ void sub_up8(float* acc, const float* __restrict__ cb,
                                        const int* __restrict__ idxn,
                                        int j, int s_up, int t_up, int tlim, int kgc) {
    float pos = (j + 0.5f) / (float)s_up - 0.5f;
    pos = fminf(fmaxf(pos, 0.0f), (float)(t_up - 1));
    int lo = (int)floorf(pos);
    int hi = min(lo + 1, t_up - 1);
    float w = pos - (float)lo;
    int ilo = (lo < tlim) ? idxn[lo] : -1;
    int ihi = (hi < tlim) ? idxn[hi] : -1;
    float wl = 1.0f - w, wh = w;
    float up[8] = {0.f, 0.f, 0.f, 0.f, 0.f, 0.f, 0.f, 0.f};
    if (ilo >= 0) {
        const float4* p = (const float4*)(cb + (size_t)ilo * Cc + kgc);
        float4 a = p[0], b = p[1];
        up[0] += wl * a.x; up[1] += wl * a.y; up[2] += wl * a.z; up[3] += wl * a.w;
        up[4] += wl * b.x; up[5] += wl * b.y; up[6] += wl * b.z; up[7] += wl * b.w;
    }
    if (ihi >= 0) {
        const float4* p = (const float4*)(cb + (size_t)ihi * Cc + kgc);
        float4 a = p[0], b = p[1];
        up[0] += wh * a.x; up[1] += wh * a.y; up[2] += wh * a.z; up[3] += wh * a.w;
        up[4] += wh * b.x; up[5] += wh * b.y; up[6] += wh * b.z; up[7] += wh * b.w;
    }
#pragma unroll
    for (int q = 0; q < 8; q++) acc[q] -= up[q];
}

// ------- pooled residual: rd = pool_s(mask * (x - up4 - up2)) ----------------
// stage 0: x only; stage 1: x - up4; stage 2: x - up4 - up2.
// Writes fp32 rows (g_rd), bf16 h-split panels (g_rdS), row norms (g_hn/g_ex).
__global__ void k_pool(const float* __restrict__ cb, const int* __restrict__ m_lens,
                       int s, int t, int stage,
                       const int* __restrict__ idx4, const int* __restrict__ idx2) {
    __shared__ float s_h2[128], s_e2[128];
    int tid = threadIdx.x, panel = blockIdx.x;
    if (tid < 128) { s_h2[tid] = 0.f; s_e2[tid] = 0.f; }
    __syncthreads();
    float inv = 1.0f / (float)s;
    for (int it = 0; it < 32; it++) {
        int item = it * 256 + tid;
        int r = item >> 6, kg = item & 63;
        int kgc = kg * 8;
        int grow = panel * 128 + r;
        int n = grow / t, tp = grow % t;
        int ml = m_lens[n];
        const int* idx4n = idx4 + n * 128;
        const int* idx2n = idx2 + n * 256;
        int tlim4 = ml >> 2, tlim2 = ml >> 1;
        float f[8] = {0.f, 0.f, 0.f, 0.f, 0.f, 0.f, 0.f, 0.f};
        for (int u = 0; u < s; u++) {
            int j = tp * s + u;
            if (j < ml) {
                const float4* s4 =
                    (const float4*)(g_xt + ((size_t)n * Tt + j) * Cc + kgc);
                float4 a = s4[0], b = s4[1];
                float acc[8] = {a.x, a.y, a.z, a.w, b.x, b.y, b.z, b.w};
                if (stage >= 1) sub_up8(acc, cb, idx4n, j, 4, 128, tlim4, kgc);
                if (stage >= 2) sub_up8(acc, cb, idx2n, j, 2, 256, tlim2, kgc);
#pragma unroll
                for (int q = 0; q < 8; q++) f[q] += acc[q];
            }
        }
#pragma unroll
        for (int q = 0; q < 8; q++) f[q] *= inv;
        // fp32 pooled row
        float4* rp = (float4*)(g_rd + (size_t)grow * Cc + kgc);
        rp[0] = make_float4(f[0], f[1], f[2], f[3]);
        rp[1] = make_float4(f[4], f[5], f[6], f[7]);
        // h split + norm partials
        union { __nv_bfloat16 bb[8]; uint4 v; } H;
        float h2 = 0.f, e2 = 0.f;
#pragma unroll
        for (int q = 0; q < 8; q++) {
            __nv_bfloat16 h = __float2bfloat16(f[q]);
            float hf = __bfloat162float(h);
            float d = f[q] - hf;
            H.bb[q] = h; h2 += hf * hf; e2 += d * d;
        }
        u32 sw = swoff(r, (kg & 7) << 4);
        char* pb = (char*)g_rdS + (size_t)panel * PANEL_BYTES
                 + (size_t)(kg >> 3) * CHUNK_BYTES + sw;
        *(uint4*)pb = H.v;
#pragma unroll
        for (int o = 16; o; o >>= 1) {
            h2 += __shfl_down_sync(0xffffffffu, h2, o);
            e2 += __shfl_down_sync(0xffffffffu, e2, o);
        }
        if ((tid & 31) == 0) {
            atomicAdd(&s_h2[r], h2);
            atomicAdd(&s_e2[r], e2);
        }
    }
    __syncthreads();
    if (tid < 128) {
        g_hn[panel * 128 + tid] = sqrtf(s_h2[tid]);
        g_ex[panel * 128 + tid] = sqrtf(s_e2[tid]);
    }
}

// ---------------- pass 1: h.h GEMM -> scores ---------------------------------
__device__ __forceinline__ void fill_stage(u32 stage, const char* A,
                                           const char* B, int tid) {
#pragma unroll
    for (int q = 0; q < 4; q++) {
        int off = (tid + q * 256) * 16;
        cpa16s(stage + off, A + off);
    }
#pragma unroll
    for (int q = 0; q < 4; q++) {
        int off = (tid + q * 256) * 16;
        cpa16s(stage + CHUNK_BYTES + off, B + off);
    }
    CP_COMMIT();
}

__global__ void __launch_bounds__(256, 2)
k_quantize6(const int* __restrict__ m_lens, int t, int scale,
            float* __restrict__ score) {
    extern __shared__ char dsm[];
    __shared__ float s_cbh[128];

    int tid = threadIdx.x, wid = tid >> 5, lane = tid & 31;
    int mbase = blockIdx.y * 128;
    int n = mbase / t;
    int tlim = m_lens[n] / scale;
    if (mbase % t >= tlim) return;           // fully masked panel

    u32 dbase = (smem_u32(dsm) + 1023) & ~1023u;
    u32 st0 = dbase, st1 = dbase + 2 * CHUNK_BYTES;

    if (tid < 128) s_cbh[tid] = g_cbhalf[blockIdx.x * 128 + tid];

    const char* A = (const char*)g_rdS + (size_t)blockIdx.y * PANEL_BYTES;
    const char* B = (const char*)g_cbS + (size_t)blockIdx.x * PANEL_BYTES;

    fill_stage(st0, A, B, tid);
    fill_stage(st1, A + CHUNK_BYTES, B + CHUNK_BYTES, tid);

    int warp_m = wid >> 2, warp_n = wid & 3;
    int sub = lane >> 3;
    int a_row = warp_m * 64 + (lane & 7) + ((sub & 1) << 3);
    int a_kb  = (sub >> 1) << 4;
    int b_row = warp_n * 32 + (lane & 7) + ((lane >> 4) << 3);
    int b_kb  = ((lane >> 3) & 1) << 4;

    float acc[4][4][4];
#pragma unroll
    for (int i = 0; i < 4; i++)
#pragma unroll
        for (int j = 0; j < 4; j++)
#pragma unroll
            for (int q = 0; q < 4; q++) acc[i][j][q] = 0.f;

    for (int i = 0; i < GCHUNK; i++) {
        if (i < GCHUNK - 1) CP_WAIT(1); else CP_WAIT(0);
        __syncthreads();
        u32 sa = (i & 1) ? st1 : st0;
        u32 sb = sa + CHUNK_BYTES;
#pragma unroll
        for (int ks = 0; ks < 4; ks++) {
            u32 af[4][4];
#pragma unroll
            for (int mt = 0; mt < 4; mt++) {
                u32 addr = sa + swoff(a_row + mt * 16, ks * 32 + a_kb);
                LDSM4(af[mt][0], af[mt][1], af[mt][2], af[mt][3], addr);
            }
            u32 bf[4][2];
#pragma unroll
            for (int pr = 0; pr < 2; pr++) {
                u32 addr = sb + swoff(b_row + pr * 16, ks * 32 + b_kb);
                LDSM4(bf[2 * pr][0], bf[2 * pr][1],
                      bf[2 * pr + 1][0], bf[2 * pr + 1][1], addr);
            }
#pragma unroll
            for (int mt = 0; mt < 4; mt++)
#pragma unroll
                for (int nt = 0; nt < 4; nt++)
                    MMA16816(acc[mt][nt], af[mt], bf[nt]);
        }
        __syncthreads();
        if (i + 2 < GCHUNK)
            fill_stage((i & 1) ? st1 : st0,
                       A + (size_t)(i + 2) * CHUNK_BYTES,
                       B + (size_t)(i + 2) * CHUNK_BYTES, tid);
    }

    int r0 = warp_m * 64 + (lane >> 2);
    int cbase = warp_n * 32 + (lane & 3) * 2;
#pragma unroll
    for (int mt = 0; mt < 4; mt++) {
#pragma unroll
        for (int nt = 0; nt < 4; nt++) {
            int cl = cbase + nt * 8;
            float h0 = s_cbh[cl], h1 = s_cbh[cl + 1];
            size_t coff = (size_t)blockIdx.x * 128 + cl;
            int grow0 = mbase + r0 + mt * 16;
            float2* o0 = (float2*)(score + (size_t)grow0 * Kk + coff);
            *o0 = make_float2(acc[mt][nt][0] - h0, acc[mt][nt][1] - h1);
            float2* o1 = (float2*)(score + (size_t)(grow0 + 8) * Kk + coff);
            *o1 = make_float2(acc[mt][nt][2] - h0, acc[mt][nt][3] - h1);
        }
    }
}

// ---------------- rescore: prune + exact fp32 argmax + hist ------------------
__global__ void k_rescore(const float* __restrict__ cb,
                          const int* __restrict__ m_lens,
                          int t, int scale, int* __restrict__ idx_out) {
    int wid = threadIdx.x >> 5, lane = threadIdx.x & 31;
    int row = blockIdx.x * 8 + wid;
    int n = row / t, tr = row % t;
    int tlim = m_lens[n] / scale;
    if (tr >= tlim) {
        if (lane == 0) idx_out[row] = 0;
        return;
    }

    float xr[16];
    const float* xrp = g_rd + (size_t)row * Cc;
#pragma unroll
    for (int c = 0; c < 16; c++) xr[c] = xrp[c * 32 + lane];

    float sc[32];
    const float* sp = g_score + (size_t)row * Kk;
#pragma unroll
    for (int j = 0; j < 32; j++) sc[j] = sp[j * 32 + lane];

    float mx = -1e30f;
#pragma unroll
    for (int j = 0; j < 32; j++) mx = fmaxf(mx, sc[j]);
#pragma unroll
    for (int o = 16; o; o >>= 1) mx = fmaxf(mx, __shfl_xor_sync(0xffffffffu, mx, o));

    float B = 1.02f * (g_hn[row] * g_Ey + g_ex[row] * (g_Hy + g_Ey)) + 1e-2f;
    float tau = mx - 2.0f * B;

    float best = -1e30f; int bi = 0;
    for (int j = 0; j < 32; j++) {
        unsigned m = __ballot_sync(0xffffffffu, sc[j] >= tau);
        while (m) {
            int l = __ffs(m) - 1; m &= m - 1;
            int k = j * 32 + l;
            const float* cbk = cb + (size_t)k * Cc;
            float p = 0.f;
#pragma unroll
            for (int c = 0; c < 16; c++) p = fmaf(xr[c], cbk[c * 32 + lane], p);
#pragma unroll
            for (int o = 16; o; o >>= 1) p += __shfl_xor_sync(0xffffffffu, p, o);
            float sv = p - g_cbhalf[k];
            if (sv > best) { best = sv; bi = k; }
        }
    }
    if (lane == 0) {
        idx_out[row] = bi;
        atomicAdd(&g_hist[bi], 1.0f);
    }
}

// ------- final: f_hat = up4+up2+up1, all three loss terms, one pass ----------
__global__ void k_final(const float* __restrict__ cb,
                        const int* __restrict__ m_lens,
                        const int* __restrict__ idx4,
                        const int* __restrict__ idx2,
                        const int* __restrict__ idx1) {
    int g = blockIdx.x;
    int n = g / Tt, j = g % Tt;
    int ml = m_lens[n];
    int i = threadIdx.x;               // 128 threads == C/4
    size_t base = ((size_t)n * Tt + j) * (Cc / 4);

    float4 u[3];
    const int* idxs[3] = {idx4 + n * 128, idx2 + n * 256, idx1 + n * 512};
    const int sups[3] = {4, 2, 1};
    const int tups[3] = {128, 256, 512};
#pragma unroll
    for (int q = 0; q < 3; q++) {
        int s_up = sups[q], t_up = tups[q];
        int tlim = ml / s_up;
        float pos = (j + 0.5f) / (float)s_up - 0.5f;
        pos = fminf(fmaxf(pos, 0.0f), (float)(t_up - 1));
        int lo = (int)floorf(pos);
        int hi = min(lo + 1, t_up - 1);
        float w = pos - (float)lo;
        int ilo = (lo < tlim) ? idxs[q][lo] : -1;
        int ihi = (hi < tlim) ? idxs[q][hi] : -1;
        float wl = 1.0f - w, wh = w;
        float4 up = make_float4(0.f, 0.f, 0.f, 0.f);
        if (ilo >= 0) {
            float4 v = ((const float4*)(cb + (size_t)ilo * Cc))[i];
            up.x += wl * v.x; up.y += wl * v.y; up.z += wl * v.z; up.w += wl * v.w;
        }
        if (ihi >= 0) {
            float4 v = ((const float4*)(cb + (size_t)ihi * Cc))[i];
            up.x += wh * v.x; up.y += wh * v.y; up.z += wh * v.z; up.w += wh * v.w;
        }
        u[q] = up;
    }
    float4 f1 = u[0];
    float4 f2 = make_float4(f1.x + u[1].x, f1.y + u[1].y, f1.z + u[1].z, f1.w + u[1].w);
    float4 f3 = make_float4(f2.x + u[2].x, f2.y + u[2].y, f2.z + u[2].z, f2.w + u[2].w);
    ((float4*)g_fhat)[base + i] = f3;

    float lsum = 0.f;
    if (j < ml) {
        float4 xv = ((const float4*)g_xt)[base + i];
        float e;
        e = xv.x - f1.x; lsum += e * e;  e = xv.y - f1.y; lsum += e * e;
        e = xv.z - f1.z; lsum += e * e;  e = xv.w - f1.w; lsum += e * e;
        e = xv.x - f2.x; lsum += e * e;  e = xv.y - f2.y; lsum += e * e;
        e = xv.z - f2.z; lsum += e * e;  e = xv.w - f2.w; lsum += e * e;
        e = xv.x - f3.x; lsum += e * e;  e = xv.y - f3.y; lsum += e * e;
        e = xv.z - f3.z; lsum += e * e;  e = xv.w - f3.w; lsum += e * e;
    }
#pragma unroll
    for (int o = 16; o; o >>= 1) lsum += __shfl_down_sync(0xffffffffu, lsum, o);
    __shared__ float ws[4];
    if ((threadIdx.x & 31) == 0) ws[threadIdx.x >> 5] = lsum;
    __syncthreads();
    if (threadIdx.x == 0 && j < ml)
        atomicAdd(&g_err[0], (double)(ws[0] + ws[1] + ws[2] + ws[3]));
}

// ---------------- finalize ---------------------------------------------------
__global__ void k_finalize(float* __restrict__ out) {
    int tid = threadIdx.x;
    float c = g_hist[tid];
    __shared__ float ws[32];
    float v = c;
#pragma unroll
    for (int o = 16; o; o >>= 1) v += __shfl_down_sync(0xffffffffu, v, o);
    if ((tid & 31) == 0) ws[tid >> 5] = v;
    __syncthreads();
    if (tid < 32) {
        float z = ws[tid];
#pragma unroll
        for (int o = 16; o; o >>= 1) z += __shfl_down_sync(0xffffffffu, z, o);
        if (tid == 0) ws[0] = z;
    }
    __syncthreads();
    float total = ws[0];
    __syncthreads();
    float p = c / total;
    float e = p * logf(p + 1e-7f);
#pragma unroll
    for (int o = 16; o; o >>= 1) e += __shfl_down_sync(0xffffffffu, e, o);
    if ((tid & 31) == 0) ws[tid >> 5] = e;
    __syncthreads();
    if (tid == 0) {
        float ent = 0.f;
        for (int i = 0; i < 32; i++) ent += ws[i];
        double denom = (double)g_masksum * (double)Tt;
        double loss = (g_err[0] + g_err[1] + g_err[2]) / denom / 3.0;
        out[NCT]     = (float)loss;
        out[NCT + 1] = expf(-ent);
    }
}

// ---------------- launch ------------------------------------------------------
extern "C" void kernel_launch(void* const* d_in, const int* in_sizes, int n_in,
                              void* d_out, int out_size) {
    const float* x = nullptr; const float* cb = nullptr; const int* m_lens = nullptr;
    for (int i = 0; i < n_in; i++) {
        if (in_sizes[i] == NCT)            x = (const float*)d_in[i];
        else if (in_sizes[i] == Kk * Cc)   cb = (const float*)d_in[i];
        else if (in_sizes[i] == Nn)        m_lens = (const int*)d_in[i];
    }
    float* out = (float*)d_out;

    const int DYN = 1024 + 4 * CHUNK_BYTES;
    cudaFuncSetAttribute(k_quantize6, cudaFuncAttributeMaxDynamicSharedMemorySize, DYN);

    void* idxv = nullptr; cudaGetSymbolAddress(&idxv, g_idx);
    int* idxbase = (int*)idxv;
    void* scv = nullptr;  cudaGetSymbolAddress(&scv, g_score);
    float* score = (float*)scv;

    int* idx4 = idxbase;
    int* idx2 = idxbase + Nn * 128;
    int* idx1 = idxbase + Nn * 128 + Nn * 256;
    int* idxs[3] = {idx4, idx2, idx1};

    k_reset_hist<<<4, 256>>>();
    k_prep_scalars<<<1, 64>>>(m_lens);
    k_cbhalf<<<Kk, 128>>>(cb);
    k_cb_split<<<8, 256>>>(cb);
    {
        dim3 gb(Tt / 32, Cc / 32, Nn), tb(32, 8);
        k_transpose_in<<<gb, tb>>>(x);
    }

    const int scales[3] = {4, 2, 1};
    for (int s = 0; s < 3; s++) {
        int sc = scales[s], t = Tt / sc, M = Nn * t;
        int panels = M / 128;
        k_pool<<<panels, 256>>>(cb, m_lens, sc, t, s, idx4, idx2);
        k_quantize6<<<dim3(8, panels), 256, DYN>>>(m_lens, t, sc, score);
        k_rescore<<<M / 8, 256>>>(cb, m_lens, t, sc, idxs[s]);
    }

    k_final<<<Nn * Tt, 128>>>(cb, m_lens, idx4, idx2, idx1);
    k_finalize<<<1, 1024>>>(out);
    {
        dim3 gb(Cc / 32, Tt / 32, Nn), tb(32, 8);
        k_transpose_out<<<gb, tb>>>(out);
    }
}